// round 1
// baseline (speedup 1.0000x reference)
#include <cuda_runtime.h>

#define BATCH 8
#define TSEQ 2048
#define CDIM 768
#define HDIM 64
#define BT_TOTAL (BATCH*TSEQ)
#define QPAD 68   // row pitch (floats) for h-major smem tiles; multiple of 4 for LDS.128

// Scratch for projected Q, K, V (fp32, [B*T, 64] each)
__device__ float g_q[BT_TOTAL*HDIM];
__device__ float g_k[BT_TOTAL*HDIM];
__device__ float g_v[BT_TOTAL*HDIM];

// ---------------------------------------------------------------------------
// Kernel 1: fused QKV projection.  out = x[16384,768] @ W[768,64]
// Block tile 64(M) x 64(N=H) x 16(K). 256 threads, 4x4 micro-tile each.
// blockIdx.y selects which of Wq/Wk/Wv.
// ---------------------------------------------------------------------------
__global__ __launch_bounds__(256) void qkv_proj(const float* __restrict__ x,
                                                const float* __restrict__ Wq,
                                                const float* __restrict__ Wk,
                                                const float* __restrict__ Wv)
{
    __shared__ float As[16][64 + 4];   // [k][m], padded
    __shared__ float Bs[16][64];       // [k][n]

    const int tid = threadIdx.x;
    const int ty = tid >> 4;           // 0..15 -> 4 M-rows each
    const int tx = tid & 15;           // 0..15 -> 4 N-cols each

    const float* W;
    float* out;
    if (blockIdx.y == 0)      { W = Wq; out = g_q; }
    else if (blockIdx.y == 1) { W = Wk; out = g_k; }
    else                      { W = Wv; out = g_v; }

    const size_t m0 = (size_t)blockIdx.x * 64;

    const int ar = tid >> 2;          // 0..63  A-tile row
    const int ac = (tid & 3) * 4;     // 0..12  A-tile k (float4)
    const int br = tid >> 4;          // 0..15  B-tile k
    const int bc = (tid & 15) * 4;    // 0..60  B-tile n (float4)

    float acc[4][4] = {};

    for (int k0 = 0; k0 < CDIM; k0 += 16) {
        float4 av = *(const float4*)(x + (m0 + ar) * CDIM + k0 + ac);
        As[ac + 0][ar] = av.x;
        As[ac + 1][ar] = av.y;
        As[ac + 2][ar] = av.z;
        As[ac + 3][ar] = av.w;
        *(float4*)&Bs[br][bc] = *(const float4*)(W + (size_t)(k0 + br) * HDIM + bc);
        __syncthreads();

        #pragma unroll
        for (int kk = 0; kk < 16; kk++) {
            float a[4], b[4];
            #pragma unroll
            for (int i = 0; i < 4; i++) a[i] = As[kk][ty * 4 + i];
            #pragma unroll
            for (int j = 0; j < 4; j++) b[j] = Bs[kk][tx * 4 + j];
            #pragma unroll
            for (int i = 0; i < 4; i++)
                #pragma unroll
                for (int j = 0; j < 4; j++)
                    acc[i][j] += a[i] * b[j];
        }
        __syncthreads();
    }

    #pragma unroll
    for (int i = 0; i < 4; i++)
        #pragma unroll
        for (int j = 0; j < 4; j++)
            out[(m0 + ty * 4 + i) * HDIM + tx * 4 + j] = acc[i][j];
}

// ---------------------------------------------------------------------------
// Kernel 2: causal flash attention over 64x64 tiles.
// One block per (q-tile, batch). 256 threads; each owns a 4x4 micro-tile.
// Smem: Qs/Ks h-major [64h][QPAD] (transposed at load), Ps [64s][QPAD],
//       Vs natural [64s][64h]. Total 68608 B dynamic.
// ---------------------------------------------------------------------------
__global__ __launch_bounds__(256) void attn_kernel(float* __restrict__ out)
{
    extern __shared__ float sm[];
    float* Qs = sm;                    // [64][QPAD]  Qs[h][r] (pre-scaled)
    float* Ks = Qs + 64 * QPAD;        // [64][QPAD]  Ks[h][c]
    float* Ps = Ks + 64 * QPAD;        // [64][QPAD]  Ps[s][r]
    float* Vs = Ps + 64 * QPAD;        // [64][64]    Vs[s][h]

    const int tid = threadIdx.x;
    const int ty = tid >> 4;   // query-row group (4 rows)
    const int tx = tid & 15;   // col group (4 cols)
    const int b  = blockIdx.y;
    const int qt = gridDim.x - 1 - blockIdx.x;   // heavy tiles launch first

    const float scale = 0.125f;   // 1/sqrt(64)

    // Load Q tile transposed (h-major), pre-scaled
    const float* qbase = g_q + ((size_t)b * TSEQ + qt * 64) * HDIM;
    for (int idx = tid; idx < 64 * 16; idx += 256) {
        int r = idx >> 4, c4 = (idx & 15) * 4;
        float4 v = *(const float4*)(qbase + r * HDIM + c4);
        Qs[(c4 + 0) * QPAD + r] = v.x * scale;
        Qs[(c4 + 1) * QPAD + r] = v.y * scale;
        Qs[(c4 + 2) * QPAD + r] = v.z * scale;
        Qs[(c4 + 3) * QPAD + r] = v.w * scale;
    }

    float m_i[4], l_i[4], o[4][4];
    #pragma unroll
    for (int i = 0; i < 4; i++) {
        m_i[i] = -1e30f; l_i[i] = 0.0f;
        #pragma unroll
        for (int j = 0; j < 4; j++) o[i][j] = 0.0f;
    }

    for (int kt = 0; kt <= qt; kt++) {
        const float* kbase = g_k + ((size_t)b * TSEQ + kt * 64) * HDIM;
        const float* vbase = g_v + ((size_t)b * TSEQ + kt * 64) * HDIM;

        __syncthreads();   // prior iter done reading Ks/Vs/Ps (also fences Q load, iter 0)
        for (int idx = tid; idx < 64 * 16; idx += 256) {
            int r = idx >> 4, c4 = (idx & 15) * 4;
            float4 kv = *(const float4*)(kbase + r * HDIM + c4);
            Ks[(c4 + 0) * QPAD + r] = kv.x;
            Ks[(c4 + 1) * QPAD + r] = kv.y;
            Ks[(c4 + 2) * QPAD + r] = kv.z;
            Ks[(c4 + 3) * QPAD + r] = kv.w;
            *(float4*)&Vs[r * 64 + c4] = *(const float4*)(vbase + r * HDIM + c4);
        }
        __syncthreads();

        // S = (scaled Q) K^T for this 64x64 tile
        float s[4][4] = {};
        #pragma unroll 8
        for (int kk = 0; kk < 64; kk++) {
            float a[4], bb[4];
            #pragma unroll
            for (int i = 0; i < 4; i++) a[i]  = Qs[kk * QPAD + ty * 4 + i];
            #pragma unroll
            for (int j = 0; j < 4; j++) bb[j] = Ks[kk * QPAD + tx * 4 + j];
            #pragma unroll
            for (int i = 0; i < 4; i++)
                #pragma unroll
                for (int j = 0; j < 4; j++)
                    s[i][j] += a[i] * bb[j];
        }

        // causal mask only on the diagonal tile
        if (kt == qt) {
            #pragma unroll
            for (int i = 0; i < 4; i++)
                #pragma unroll
                for (int j = 0; j < 4; j++)
                    if (tx * 4 + j > ty * 4 + i) s[i][j] = -1e30f;
        }

        // online softmax (row stats across the 16-lane tx group)
        #pragma unroll
        for (int i = 0; i < 4; i++) {
            float mx = fmaxf(fmaxf(s[i][0], s[i][1]), fmaxf(s[i][2], s[i][3]));
            #pragma unroll
            for (int off = 1; off < 16; off <<= 1)
                mx = fmaxf(mx, __shfl_xor_sync(0xffffffffu, mx, off));
            float mnew = fmaxf(m_i[i], mx);
            float alpha = __expf(m_i[i] - mnew);
            float rs = 0.0f;
            #pragma unroll
            for (int j = 0; j < 4; j++) {
                s[i][j] = __expf(s[i][j] - mnew);
                rs += s[i][j];
            }
            #pragma unroll
            for (int off = 1; off < 16; off <<= 1)
                rs += __shfl_xor_sync(0xffffffffu, rs, off);
            l_i[i] = l_i[i] * alpha + rs;
            m_i[i] = mnew;
            #pragma unroll
            for (int j = 0; j < 4; j++) o[i][j] *= alpha;
        }

        // stage P (transposed: Ps[s][r]) for the PV GEMM
        #pragma unroll
        for (int i = 0; i < 4; i++)
            #pragma unroll
            for (int j = 0; j < 4; j++)
                Ps[(tx * 4 + j) * QPAD + ty * 4 + i] = s[i][j];
        __syncthreads();

        // O += P V
        #pragma unroll 8
        for (int ss = 0; ss < 64; ss++) {
            float p[4], vv[4];
            #pragma unroll
            for (int i = 0; i < 4; i++) p[i]  = Ps[ss * QPAD + ty * 4 + i];
            #pragma unroll
            for (int j = 0; j < 4; j++) vv[j] = Vs[ss * 64 + tx * 4 + j];
            #pragma unroll
            for (int i = 0; i < 4; i++)
                #pragma unroll
                for (int j = 0; j < 4; j++)
                    o[i][j] += p[i] * vv[j];
        }
    }

    float* ob = out + ((size_t)b * TSEQ + qt * 64) * HDIM;
    #pragma unroll
    for (int i = 0; i < 4; i++) {
        float inv = 1.0f / l_i[i];
        #pragma unroll
        for (int j = 0; j < 4; j++)
            ob[(ty * 4 + i) * HDIM + tx * 4 + j] = o[i][j] * inv;
    }
}

// ---------------------------------------------------------------------------
extern "C" void kernel_launch(void* const* d_in, const int* in_sizes, int n_in,
                              void* d_out, int out_size)
{
    (void)in_sizes; (void)n_in; (void)out_size;
    const float* x  = (const float*)d_in[0];
    const float* Wq = (const float*)d_in[1];
    const float* Wk = (const float*)d_in[2];
    const float* Wv = (const float*)d_in[3];
    float* out = (float*)d_out;

    const int attn_smem = (3 * 64 * QPAD + 64 * 64) * (int)sizeof(float);  // 68608
    cudaFuncSetAttribute(attn_kernel, cudaFuncAttributeMaxDynamicSharedMemorySize,
                         attn_smem);

    dim3 gproj(BT_TOTAL / 64, 3);
    qkv_proj<<<gproj, 256>>>(x, Wq, Wk, Wv);

    dim3 gattn(TSEQ / 64, BATCH);
    attn_kernel<<<gattn, 256, attn_smem>>>(out);
}

// round 2
// speedup vs baseline: 2.5834x; 2.5834x over previous
#include <cuda_runtime.h>

#define BATCH 8
#define TSEQ 2048
#define CDIM 768
#define HDIM 64
#define BT_TOTAL (BATCH*TSEQ)

// Scratch for projected Q, K, V (fp32, [B*T, 64] each)
__device__ float g_q[BT_TOTAL*HDIM];
__device__ float g_k[BT_TOTAL*HDIM];
__device__ float g_v[BT_TOTAL*HDIM];

// ---------------------------------------------------------------------------
// tf32 helpers
// ---------------------------------------------------------------------------
__device__ __forceinline__ unsigned f2tf(float f) {
    unsigned u;
    asm("cvt.rna.tf32.f32 %0, %1;" : "=r"(u) : "f"(f));
    return u;
}

__device__ __forceinline__ void mma_tf32(float c[4],
                                         unsigned a0, unsigned a1, unsigned a2, unsigned a3,
                                         unsigned b0, unsigned b1) {
    asm volatile(
        "mma.sync.aligned.m16n8k8.row.col.f32.tf32.tf32.f32 "
        "{%0,%1,%2,%3},{%4,%5,%6,%7},{%8,%9},{%0,%1,%2,%3};"
        : "+f"(c[0]), "+f"(c[1]), "+f"(c[2]), "+f"(c[3])
        : "r"(a0), "r"(a1), "r"(a2), "r"(a3), "r"(b0), "r"(b1));
}

// ---------------------------------------------------------------------------
// Kernel 1: fused QKV projection.  out = x[16384,768] @ W[768,64]  (tf32 mma)
// Block: 256 threads (8 warps), tile M=128 x N=64, K-chunks of 32.
// Warp w owns rows w*16..w*16+15 (m16), all 8 n8 tiles.
// ---------------------------------------------------------------------------
#define XPITCH 36   // 32 + 4: A-frag banks = 4*row + t  -> conflict-free
#define WPITCH 68   // 64 + 4: B-frag banks = 4*t + n    -> conflict-free

__global__ __launch_bounds__(256) void qkv_proj(const float* __restrict__ x,
                                                const float* __restrict__ Wq,
                                                const float* __restrict__ Wk,
                                                const float* __restrict__ Wv)
{
    __shared__ float Xs[128 * XPITCH];
    __shared__ float Ws[32 * WPITCH];

    const int tid  = threadIdx.x;
    const int w    = tid >> 5;        // warp 0..7
    const int lane = tid & 31;
    const int g    = lane >> 2;       // group 0..7
    const int t    = lane & 3;        // 0..3

    const float* W;
    float* out;
    if (blockIdx.y == 0)      { W = Wq; out = g_q; }
    else if (blockIdx.y == 1) { W = Wk; out = g_k; }
    else                      { W = Wv; out = g_v; }

    const size_t m0 = (size_t)blockIdx.x * 128;
    const int mw = w * 16;

    float acc[8][4];
    #pragma unroll
    for (int j = 0; j < 8; j++)
        #pragma unroll
        for (int c = 0; c < 4; c++) acc[j][c] = 0.0f;

    for (int kc = 0; kc < CDIM; kc += 32) {
        // stage x tile [128][32] and W tile [32][64]
        #pragma unroll
        for (int rep = 0; rep < 4; rep++) {
            int e = tid + rep * 256;           // < 1024
            int m = e >> 3, c4 = (e & 7) * 4;
            *(float4*)&Xs[m * XPITCH + c4] =
                *(const float4*)(x + (m0 + m) * CDIM + kc + c4);
        }
        #pragma unroll
        for (int rep = 0; rep < 2; rep++) {
            int e = tid + rep * 256;           // < 512
            int r = e >> 4, c4 = (e & 15) * 4;
            *(float4*)&Ws[r * WPITCH + c4] =
                *(const float4*)(W + (size_t)(kc + r) * HDIM + c4);
        }
        __syncthreads();

        #pragma unroll
        for (int ks = 0; ks < 4; ks++) {
            const int kk = ks * 8;
            unsigned a0 = f2tf(Xs[(mw + g)     * XPITCH + kk + t]);
            unsigned a1 = f2tf(Xs[(mw + g + 8) * XPITCH + kk + t]);
            unsigned a2 = f2tf(Xs[(mw + g)     * XPITCH + kk + t + 4]);
            unsigned a3 = f2tf(Xs[(mw + g + 8) * XPITCH + kk + t + 4]);
            #pragma unroll
            for (int j = 0; j < 8; j++) {
                unsigned b0 = f2tf(Ws[(kk + t)     * WPITCH + j * 8 + g]);
                unsigned b1 = f2tf(Ws[(kk + t + 4) * WPITCH + j * 8 + g]);
                mma_tf32(acc[j], a0, a1, a2, a3, b0, b1);
            }
        }
        __syncthreads();
    }

    // store: C layout -> rows (g, g+8), cols (2t, 2t+1) within n8 tile j
    #pragma unroll
    for (int j = 0; j < 8; j++) {
        float2 lo = make_float2(acc[j][0], acc[j][1]);
        float2 hi = make_float2(acc[j][2], acc[j][3]);
        *(float2*)(out + (m0 + mw + g)     * HDIM + j * 8 + 2 * t) = lo;
        *(float2*)(out + (m0 + mw + g + 8) * HDIM + j * 8 + 2 * t) = hi;
    }
}

// ---------------------------------------------------------------------------
// Kernel 2: causal flash attention, tf32 mma, 64x64 tiles.
// 128 threads = 4 warps, warp w owns query rows w*16..+15 of the tile.
// S and O accumulators in registers (C layout); register online softmax;
// P staged per-warp through smem for the C->A layout change.
// ---------------------------------------------------------------------------
#define APITCH 68   // 64 + 4

__global__ __launch_bounds__(128) void attn_kernel(float* __restrict__ out)
{
    extern __shared__ float sm[];
    float* Qs = sm;                    // [64][APITCH]  natural [row][h]
    float* Ks = Qs + 64 * APITCH;      // [64][APITCH]  natural [s][h]
    float* Vs = Ks + 64 * APITCH;      // [64][APITCH]  natural [s][h]
    float* Ps = Vs + 64 * APITCH;      // [64][APITCH]  [row][s], per-warp rows

    const int tid  = threadIdx.x;
    const int w    = tid >> 5;
    const int lane = tid & 31;
    const int g    = lane >> 2;
    const int t    = lane & 3;
    const int b    = blockIdx.y;
    const int qt   = gridDim.x - 1 - blockIdx.x;   // heavy tiles first
    const int mw   = w * 16;

    // load Q tile (natural layout)
    const float* qbase = g_q + ((size_t)b * TSEQ + qt * 64) * HDIM;
    #pragma unroll
    for (int rep = 0; rep < 8; rep++) {
        int e = tid + rep * 128;
        int r = e >> 4, c4 = (e & 15) * 4;
        *(float4*)&Qs[r * APITCH + c4] = *(const float4*)(qbase + r * HDIM + c4);
    }

    float m_i[2] = {-1e30f, -1e30f};
    float l_i[2] = {0.0f, 0.0f};
    float o[8][4];
    #pragma unroll
    for (int j = 0; j < 8; j++)
        #pragma unroll
        for (int c = 0; c < 4; c++) o[j][c] = 0.0f;

    for (int kt = 0; kt <= qt; kt++) {
        const float* kbase = g_k + ((size_t)b * TSEQ + kt * 64) * HDIM;
        const float* vbase = g_v + ((size_t)b * TSEQ + kt * 64) * HDIM;

        __syncthreads();   // previous iter done with Ks/Vs (iter0: fences Q too)
        #pragma unroll
        for (int rep = 0; rep < 8; rep++) {
            int e = tid + rep * 128;
            int r = e >> 4, c4 = (e & 15) * 4;
            *(float4*)&Ks[r * APITCH + c4] = *(const float4*)(kbase + r * HDIM + c4);
            *(float4*)&Vs[r * APITCH + c4] = *(const float4*)(vbase + r * HDIM + c4);
        }
        __syncthreads();

        // ---- S = Q K^T (tf32 mma), S tile n8 index j covers s-cols j*8.. ----
        float s[8][4];
        #pragma unroll
        for (int j = 0; j < 8; j++)
            #pragma unroll
            for (int c = 0; c < 4; c++) s[j][c] = 0.0f;

        #pragma unroll
        for (int ks = 0; ks < 8; ks++) {
            const int kk = ks * 8;
            unsigned a0 = f2tf(Qs[(mw + g)     * APITCH + kk + t]);
            unsigned a1 = f2tf(Qs[(mw + g + 8) * APITCH + kk + t]);
            unsigned a2 = f2tf(Qs[(mw + g)     * APITCH + kk + t + 4]);
            unsigned a3 = f2tf(Qs[(mw + g + 8) * APITCH + kk + t + 4]);
            #pragma unroll
            for (int j = 0; j < 8; j++) {
                // B(k=h, n=s) = K[s][h]
                unsigned b0 = f2tf(Ks[(j * 8 + g) * APITCH + kk + t]);
                unsigned b1 = f2tf(Ks[(j * 8 + g) * APITCH + kk + t + 4]);
                mma_tf32(s[j], a0, a1, a2, a3, b0, b1);
            }
        }

        // scale + causal mask (diagonal tile only)
        const float scale = 0.125f;
        if (kt == qt) {
            #pragma unroll
            for (int j = 0; j < 8; j++)
                #pragma unroll
                for (int c = 0; c < 4; c++) {
                    int col = j * 8 + 2 * t + (c & 1);
                    int row = mw + g + ((c >> 1) << 3);
                    s[j][c] = (col > row) ? -1e30f : s[j][c] * scale;
                }
        } else {
            #pragma unroll
            for (int j = 0; j < 8; j++)
                #pragma unroll
                for (int c = 0; c < 4; c++) s[j][c] *= scale;
        }

        // ---- online softmax per row-half (rows g and g+8) ----
        #pragma unroll
        for (int h = 0; h < 2; h++) {
            const int c0 = h * 2, c1 = h * 2 + 1;
            float mx = -1e30f;
            #pragma unroll
            for (int j = 0; j < 8; j++)
                mx = fmaxf(mx, fmaxf(s[j][c0], s[j][c1]));
            mx = fmaxf(mx, __shfl_xor_sync(0xffffffffu, mx, 1));
            mx = fmaxf(mx, __shfl_xor_sync(0xffffffffu, mx, 2));
            float mnew = fmaxf(m_i[h], mx);
            float alpha = __expf(m_i[h] - mnew);
            float rs = 0.0f;
            #pragma unroll
            for (int j = 0; j < 8; j++) {
                s[j][c0] = __expf(s[j][c0] - mnew);
                s[j][c1] = __expf(s[j][c1] - mnew);
                rs += s[j][c0] + s[j][c1];
            }
            rs += __shfl_xor_sync(0xffffffffu, rs, 1);
            rs += __shfl_xor_sync(0xffffffffu, rs, 2);
            l_i[h] = l_i[h] * alpha + rs;
            m_i[h] = mnew;
            #pragma unroll
            for (int j = 0; j < 8; j++) { o[j][c0] *= alpha; o[j][c1] *= alpha; }
        }

        // ---- stage P (C layout -> [row][s] in per-warp smem rows) ----
        #pragma unroll
        for (int j = 0; j < 8; j++) {
            *(float2*)&Ps[(mw + g)     * APITCH + j * 8 + 2 * t] = make_float2(s[j][0], s[j][1]);
            *(float2*)&Ps[(mw + g + 8) * APITCH + j * 8 + 2 * t] = make_float2(s[j][2], s[j][3]);
        }
        __syncwarp();

        // ---- O += P V  (A = P [m16 x k=s], B = V (k=s, n=h)) ----
        #pragma unroll
        for (int ks = 0; ks < 8; ks++) {
            const int kk = ks * 8;
            unsigned a0 = f2tf(Ps[(mw + g)     * APITCH + kk + t]);
            unsigned a1 = f2tf(Ps[(mw + g + 8) * APITCH + kk + t]);
            unsigned a2 = f2tf(Ps[(mw + g)     * APITCH + kk + t + 4]);
            unsigned a3 = f2tf(Ps[(mw + g + 8) * APITCH + kk + t + 4]);
            #pragma unroll
            for (int j = 0; j < 8; j++) {
                unsigned b0 = f2tf(Vs[(kk + t)     * APITCH + j * 8 + g]);
                unsigned b1 = f2tf(Vs[(kk + t + 4) * APITCH + j * 8 + g]);
                mma_tf32(o[j], a0, a1, a2, a3, b0, b1);
            }
        }
    }

    // ---- normalize + store ----
    float* ob = out + ((size_t)b * TSEQ + qt * 64) * HDIM;
    float inv0 = 1.0f / l_i[0];
    float inv1 = 1.0f / l_i[1];
    #pragma unroll
    for (int j = 0; j < 8; j++) {
        *(float2*)(ob + (mw + g)     * HDIM + j * 8 + 2 * t) =
            make_float2(o[j][0] * inv0, o[j][1] * inv0);
        *(float2*)(ob + (mw + g + 8) * HDIM + j * 8 + 2 * t) =
            make_float2(o[j][2] * inv1, o[j][3] * inv1);
    }
}

// ---------------------------------------------------------------------------
extern "C" void kernel_launch(void* const* d_in, const int* in_sizes, int n_in,
                              void* d_out, int out_size)
{
    (void)in_sizes; (void)n_in; (void)out_size;
    const float* x  = (const float*)d_in[0];
    const float* Wq = (const float*)d_in[1];
    const float* Wk = (const float*)d_in[2];
    const float* Wv = (const float*)d_in[3];
    float* out = (float*)d_out;

    const int attn_smem = 4 * 64 * APITCH * (int)sizeof(float);  // 69632
    cudaFuncSetAttribute(attn_kernel, cudaFuncAttributeMaxDynamicSharedMemorySize,
                         attn_smem);

    dim3 gproj(BT_TOTAL / 128, 3);
    qkv_proj<<<gproj, 256>>>(x, Wq, Wk, Wv);

    dim3 gattn(TSEQ / 64, BATCH);
    attn_kernel<<<gattn, 128, attn_smem>>>(out);
}

// round 3
// speedup vs baseline: 2.7412x; 1.0611x over previous
#include <cuda_runtime.h>

#define BATCH 8
#define TSEQ 2048
#define CDIM 768
#define HDIM 64
#define BT_TOTAL (BATCH*TSEQ)

// Scratch for projected Q, K, V. Values are ALREADY tf32-rounded (and Q is
// pre-scaled by 1/sqrt(H) * log2(e) so attention uses exp2 directly).
__device__ float g_q[BT_TOTAL*HDIM];
__device__ float g_k[BT_TOTAL*HDIM];
__device__ float g_v[BT_TOTAL*HDIM];

// ---------------------------------------------------------------------------
// tf32 helpers
// ---------------------------------------------------------------------------
__device__ __forceinline__ unsigned f2tf(float f) {
    unsigned u;
    asm("cvt.rna.tf32.f32 %0, %1;" : "=r"(u) : "f"(f));
    return u;
}
__device__ __forceinline__ unsigned bits(float f) { return __float_as_uint(f); }

__device__ __forceinline__ void mma_tf32(float c[4],
                                         unsigned a0, unsigned a1, unsigned a2, unsigned a3,
                                         unsigned b0, unsigned b1) {
    asm volatile(
        "mma.sync.aligned.m16n8k8.row.col.f32.tf32.tf32.f32 "
        "{%0,%1,%2,%3},{%4,%5,%6,%7},{%8,%9},{%0,%1,%2,%3};"
        : "+f"(c[0]), "+f"(c[1]), "+f"(c[2]), "+f"(c[3])
        : "r"(a0), "r"(a1), "r"(a2), "r"(a3), "r"(b0), "r"(b1));
}

// ---------------------------------------------------------------------------
// Kernel 1: fused QKV projection. out = x[16384,768] @ W[768,64] (tf32 mma)
// 256 threads (8 warps), tile M=128 x N=64, K-chunks of 32.
// tf32 conversion happens ONCE at smem-stage time; mma consumes raw bits.
// Output is stored tf32-rounded; Q additionally pre-scaled by 0.125*log2(e).
// ---------------------------------------------------------------------------
#define XPITCH 36
#define WPITCH 68

__global__ __launch_bounds__(256) void qkv_proj(const float* __restrict__ x,
                                                const float* __restrict__ Wq,
                                                const float* __restrict__ Wk,
                                                const float* __restrict__ Wv)
{
    __shared__ float Xs[128 * XPITCH];
    __shared__ float Ws[32 * WPITCH];

    const int tid  = threadIdx.x;
    const int w    = tid >> 5;
    const int lane = tid & 31;
    const int g    = lane >> 2;
    const int t    = lane & 3;

    const float* W;
    float* out;
    float oscale;
    if (blockIdx.y == 0)      { W = Wq; out = g_q; oscale = 0.18033688011112042f; } // 0.125*log2(e)
    else if (blockIdx.y == 1) { W = Wk; out = g_k; oscale = 1.0f; }
    else                      { W = Wv; out = g_v; oscale = 1.0f; }

    const size_t m0 = (size_t)blockIdx.x * 128;
    const int mw = w * 16;

    float acc[8][4];
    #pragma unroll
    for (int j = 0; j < 8; j++)
        #pragma unroll
        for (int c = 0; c < 4; c++) acc[j][c] = 0.0f;

    for (int kc = 0; kc < CDIM; kc += 32) {
        #pragma unroll
        for (int rep = 0; rep < 4; rep++) {
            int e = tid + rep * 256;
            int m = e >> 3, c4 = (e & 7) * 4;
            float4 v = *(const float4*)(x + (m0 + m) * CDIM + kc + c4);
            v.x = __uint_as_float(f2tf(v.x));
            v.y = __uint_as_float(f2tf(v.y));
            v.z = __uint_as_float(f2tf(v.z));
            v.w = __uint_as_float(f2tf(v.w));
            *(float4*)&Xs[m * XPITCH + c4] = v;
        }
        #pragma unroll
        for (int rep = 0; rep < 2; rep++) {
            int e = tid + rep * 256;
            int r = e >> 4, c4 = (e & 15) * 4;
            float4 v = *(const float4*)(W + (size_t)(kc + r) * HDIM + c4);
            v.x = __uint_as_float(f2tf(v.x));
            v.y = __uint_as_float(f2tf(v.y));
            v.z = __uint_as_float(f2tf(v.z));
            v.w = __uint_as_float(f2tf(v.w));
            *(float4*)&Ws[r * WPITCH + c4] = v;
        }
        __syncthreads();

        #pragma unroll
        for (int ks = 0; ks < 4; ks++) {
            const int kk = ks * 8;
            unsigned a0 = bits(Xs[(mw + g)     * XPITCH + kk + t]);
            unsigned a1 = bits(Xs[(mw + g + 8) * XPITCH + kk + t]);
            unsigned a2 = bits(Xs[(mw + g)     * XPITCH + kk + t + 4]);
            unsigned a3 = bits(Xs[(mw + g + 8) * XPITCH + kk + t + 4]);
            #pragma unroll
            for (int j = 0; j < 8; j++) {
                unsigned b0 = bits(Ws[(kk + t)     * WPITCH + j * 8 + g]);
                unsigned b1 = bits(Ws[(kk + t + 4) * WPITCH + j * 8 + g]);
                mma_tf32(acc[j], a0, a1, a2, a3, b0, b1);
            }
        }
        __syncthreads();
    }

    // store tf32-rounded (and Q pre-scaled)
    #pragma unroll
    for (int j = 0; j < 8; j++) {
        float2 lo = make_float2(__uint_as_float(f2tf(acc[j][0] * oscale)),
                                __uint_as_float(f2tf(acc[j][1] * oscale)));
        float2 hi = make_float2(__uint_as_float(f2tf(acc[j][2] * oscale)),
                                __uint_as_float(f2tf(acc[j][3] * oscale)));
        *(float2*)(out + (m0 + mw + g)     * HDIM + j * 8 + 2 * t) = lo;
        *(float2*)(out + (m0 + mw + g + 8) * HDIM + j * 8 + 2 * t) = hi;
    }
}

// ---------------------------------------------------------------------------
// Kernel 2: causal flash attention, tf32 mma, 64x64 tiles, zero cvts in loop.
// 128 threads = 4 warps. Q fragments live in registers (loaded once); the Q
// smem region is reused as the P staging buffer. exp2-domain softmax.
// ---------------------------------------------------------------------------
#define APITCH 68

__global__ __launch_bounds__(128) void attn_kernel(float* __restrict__ out)
{
    extern __shared__ float sm[];
    float* Ks  = sm;                   // [64][APITCH] natural [s][h]
    float* Vs  = Ks + 64 * APITCH;     // [64][APITCH] natural [s][h]
    float* QPs = Vs + 64 * APITCH;     // [64][APITCH] Q tile, then P staging

    const int tid  = threadIdx.x;
    const int w    = tid >> 5;
    const int lane = tid & 31;
    const int g    = lane >> 2;
    const int t    = lane & 3;
    const int b    = blockIdx.y;
    const int qt   = gridDim.x - 1 - blockIdx.x;   // heavy tiles first
    const int mw   = w * 16;

    // ---- load Q tile, then hoist fragments into registers ----
    const float* qbase = g_q + ((size_t)b * TSEQ + qt * 64) * HDIM;
    #pragma unroll
    for (int rep = 0; rep < 8; rep++) {
        int e = tid + rep * 128;
        int r = e >> 4, c4 = (e & 15) * 4;
        *(float4*)&QPs[r * APITCH + c4] = *(const float4*)(qbase + r * HDIM + c4);
    }
    __syncthreads();

    unsigned qa[8][4];
    #pragma unroll
    for (int ks = 0; ks < 8; ks++) {
        const int kk = ks * 8;
        qa[ks][0] = bits(QPs[(mw + g)     * APITCH + kk + t]);
        qa[ks][1] = bits(QPs[(mw + g + 8) * APITCH + kk + t]);
        qa[ks][2] = bits(QPs[(mw + g)     * APITCH + kk + t + 4]);
        qa[ks][3] = bits(QPs[(mw + g + 8) * APITCH + kk + t + 4]);
    }

    float m_i[2] = {-1e30f, -1e30f};
    float l_i[2] = {0.0f, 0.0f};
    float o[8][4];
    #pragma unroll
    for (int j = 0; j < 8; j++)
        #pragma unroll
        for (int c = 0; c < 4; c++) o[j][c] = 0.0f;

    for (int kt = 0; kt <= qt; kt++) {
        const float* kbase = g_k + ((size_t)b * TSEQ + kt * 64) * HDIM;
        const float* vbase = g_v + ((size_t)b * TSEQ + kt * 64) * HDIM;

        __syncthreads();   // previous iter done reading Ks/Vs
        #pragma unroll
        for (int rep = 0; rep < 8; rep++) {
            int e = tid + rep * 128;
            int r = e >> 4, c4 = (e & 15) * 4;
            *(float4*)&Ks[r * APITCH + c4] = *(const float4*)(kbase + r * HDIM + c4);
            *(float4*)&Vs[r * APITCH + c4] = *(const float4*)(vbase + r * HDIM + c4);
        }
        __syncthreads();

        // ---- S = Q K^T : logits already scaled to exp2 domain ----
        float s[8][4];
        #pragma unroll
        for (int j = 0; j < 8; j++)
            #pragma unroll
            for (int c = 0; c < 4; c++) s[j][c] = 0.0f;

        #pragma unroll
        for (int ks = 0; ks < 8; ks++) {
            const int kk = ks * 8;
            #pragma unroll
            for (int j = 0; j < 8; j++) {
                unsigned b0 = bits(Ks[(j * 8 + g) * APITCH + kk + t]);
                unsigned b1 = bits(Ks[(j * 8 + g) * APITCH + kk + t + 4]);
                mma_tf32(s[j], qa[ks][0], qa[ks][1], qa[ks][2], qa[ks][3], b0, b1);
            }
        }

        // causal mask (diagonal tile only)
        if (kt == qt) {
            #pragma unroll
            for (int j = 0; j < 8; j++)
                #pragma unroll
                for (int c = 0; c < 4; c++) {
                    int col = j * 8 + 2 * t + (c & 1);
                    int row = mw + g + ((c >> 1) << 3);
                    if (col > row) s[j][c] = -1e30f;
                }
        }

        // ---- online softmax (exp2 domain), rows g and g+8 ----
        #pragma unroll
        for (int h = 0; h < 2; h++) {
            const int c0 = h * 2, c1 = h * 2 + 1;
            float mx = -1e30f;
            #pragma unroll
            for (int j = 0; j < 8; j++)
                mx = fmaxf(mx, fmaxf(s[j][c0], s[j][c1]));
            mx = fmaxf(mx, __shfl_xor_sync(0xffffffffu, mx, 1));
            mx = fmaxf(mx, __shfl_xor_sync(0xffffffffu, mx, 2));
            float mnew = fmaxf(m_i[h], mx);
            float alpha = exp2f(m_i[h] - mnew);
            float rs = 0.0f;
            #pragma unroll
            for (int j = 0; j < 8; j++) {
                s[j][c0] = exp2f(s[j][c0] - mnew);
                s[j][c1] = exp2f(s[j][c1] - mnew);
                rs += s[j][c0] + s[j][c1];
            }
            rs += __shfl_xor_sync(0xffffffffu, rs, 1);
            rs += __shfl_xor_sync(0xffffffffu, rs, 2);
            l_i[h] = l_i[h] * alpha + rs;
            m_i[h] = mnew;
            #pragma unroll
            for (int j = 0; j < 8; j++) { o[j][c0] *= alpha; o[j][c1] *= alpha; }
        }

        // ---- stage P (tf32-rounded) into per-warp rows of QPs ----
        #pragma unroll
        for (int j = 0; j < 8; j++) {
            *(float2*)&QPs[(mw + g)     * APITCH + j * 8 + 2 * t] =
                make_float2(__uint_as_float(f2tf(s[j][0])), __uint_as_float(f2tf(s[j][1])));
            *(float2*)&QPs[(mw + g + 8) * APITCH + j * 8 + 2 * t] =
                make_float2(__uint_as_float(f2tf(s[j][2])), __uint_as_float(f2tf(s[j][3])));
        }
        __syncwarp();

        // ---- O += P V ----
        #pragma unroll
        for (int ks = 0; ks < 8; ks++) {
            const int kk = ks * 8;
            unsigned a0 = bits(QPs[(mw + g)     * APITCH + kk + t]);
            unsigned a1 = bits(QPs[(mw + g + 8) * APITCH + kk + t]);
            unsigned a2 = bits(QPs[(mw + g)     * APITCH + kk + t + 4]);
            unsigned a3 = bits(QPs[(mw + g + 8) * APITCH + kk + t + 4]);
            #pragma unroll
            for (int j = 0; j < 8; j++) {
                unsigned b0 = bits(Vs[(kk + t)     * APITCH + j * 8 + g]);
                unsigned b1 = bits(Vs[(kk + t + 4) * APITCH + j * 8 + g]);
                mma_tf32(o[j], a0, a1, a2, a3, b0, b1);
            }
        }
    }

    // ---- normalize + store ----
    float* ob = out + ((size_t)b * TSEQ + qt * 64) * HDIM;
    float inv0 = 1.0f / l_i[0];
    float inv1 = 1.0f / l_i[1];
    #pragma unroll
    for (int j = 0; j < 8; j++) {
        *(float2*)(ob + (mw + g)     * HDIM + j * 8 + 2 * t) =
            make_float2(o[j][0] * inv0, o[j][1] * inv0);
        *(float2*)(ob + (mw + g + 8) * HDIM + j * 8 + 2 * t) =
            make_float2(o[j][2] * inv1, o[j][3] * inv1);
    }
}

// ---------------------------------------------------------------------------
extern "C" void kernel_launch(void* const* d_in, const int* in_sizes, int n_in,
                              void* d_out, int out_size)
{
    (void)in_sizes; (void)n_in; (void)out_size;
    const float* x  = (const float*)d_in[0];
    const float* Wq = (const float*)d_in[1];
    const float* Wk = (const float*)d_in[2];
    const float* Wv = (const float*)d_in[3];
    float* out = (float*)d_out;

    const int attn_smem = 3 * 64 * APITCH * (int)sizeof(float);  // 52224
    cudaFuncSetAttribute(attn_kernel, cudaFuncAttributeMaxDynamicSharedMemorySize,
                         attn_smem);

    dim3 gproj(BT_TOTAL / 128, 3);
    qkv_proj<<<gproj, 256>>>(x, Wq, Wk, Wv);

    dim3 gattn(TSEQ / 64, BATCH);
    attn_kernel<<<gattn, 128, attn_smem>>>(out);
}

// round 4
// speedup vs baseline: 3.0649x; 1.1181x over previous
#include <cuda_runtime.h>

#define BATCH 8
#define TSEQ 2048
#define CDIM 768
#define HDIM 64
#define BT_TOTAL (BATCH*TSEQ)

// Projected Q, K (natural [b][s][h]) and V (TRANSPOSED [b][h][s]).
// All values already tf32-RNA-rounded; Q pre-scaled by 0.125*log2(e).
__device__ float g_q[BT_TOTAL*HDIM];
__device__ float g_k[BT_TOTAL*HDIM];
__device__ float g_v[BT_TOTAL*HDIM];

// ---------------------------------------------------------------------------
// helpers
// ---------------------------------------------------------------------------
__device__ __forceinline__ unsigned f2tf(float f) {
    unsigned u;
    asm("cvt.rna.tf32.f32 %0, %1;" : "=r"(u) : "f"(f));
    return u;
}
__device__ __forceinline__ float f2tff(float f) { return __uint_as_float(f2tf(f)); }
__device__ __forceinline__ unsigned bits(float f) { return __float_as_uint(f); }

__device__ __forceinline__ void mma_tf32(float c[4],
                                         unsigned a0, unsigned a1, unsigned a2, unsigned a3,
                                         unsigned b0, unsigned b1) {
    asm volatile(
        "mma.sync.aligned.m16n8k8.row.col.f32.tf32.tf32.f32 "
        "{%0,%1,%2,%3},{%4,%5,%6,%7},{%8,%9},{%0,%1,%2,%3};"
        : "+f"(c[0]), "+f"(c[1]), "+f"(c[2]), "+f"(c[3])
        : "r"(a0), "r"(a1), "r"(a2), "r"(a3), "r"(b0), "r"(b1));
}

__device__ __forceinline__ void ldsm4(unsigned &r0, unsigned &r1, unsigned &r2, unsigned &r3,
                                      const float* p) {
    unsigned a = (unsigned)__cvta_generic_to_shared(p);
    asm volatile("ldmatrix.sync.aligned.m8n8.x4.shared.b16 {%0,%1,%2,%3}, [%4];"
                 : "=r"(r0), "=r"(r1), "=r"(r2), "=r"(r3) : "r"(a));
}

__device__ __forceinline__ void cpasync16(float* dst, const float* src) {
    unsigned a = (unsigned)__cvta_generic_to_shared(dst);
    asm volatile("cp.async.cg.shared.global [%0], [%1], 16;" :: "r"(a), "l"(src));
}
#define CP_COMMIT() asm volatile("cp.async.commit_group;")
template<int N> __device__ __forceinline__ void cp_wait() {
    asm volatile("cp.async.wait_group %0;" :: "n"(N));
}

// ---------------------------------------------------------------------------
// Kernel 1: QKV projection.  out = x[16384,768] @ W[768,64]   (tf32 mma)
// 256 threads / 8 warps, tile M=128 x N=64, K-chunk 64.
// x and W are RNA-rounded at smem-stage time (W staged transposed [n][k]).
// Q,K stored natural; V stored transposed [b][h][s]. All outputs tf32-rounded.
// ---------------------------------------------------------------------------
#define PPITCH 68

__global__ __launch_bounds__(256) void qkv_proj(const float* __restrict__ x,
                                                const float* __restrict__ Wq,
                                                const float* __restrict__ Wk,
                                                const float* __restrict__ Wv)
{
    __shared__ float Xs[128 * PPITCH];   // [m][k]
    __shared__ float Ws[64 * PPITCH];    // [n][k]  (transposed at stage)

    const int tid  = threadIdx.x;
    const int w    = tid >> 5;
    const int lane = tid & 31;
    const int mw   = w * 16;
    const int lrow = lane & 7;

    // ldmatrix lane patterns (pitch PPITCH):
    const int idxA = ((((lane >> 3) & 1) * 8 + lrow)) * PPITCH + ((lane >> 4) & 1) * 4;
    const int idxB = ((((lane >> 4) & 1) * 8 + lrow)) * PPITCH + ((lane >> 3) & 1) * 4;

    const float* W;
    float oscale;
    if (blockIdx.y == 0)      { W = Wq; oscale = 0.18033688011112042f; } // 0.125*log2(e)
    else if (blockIdx.y == 1) { W = Wk; oscale = 1.0f; }
    else                      { W = Wv; oscale = 1.0f; }

    const size_t m0 = (size_t)blockIdx.x * 128;

    float acc[8][4];
    #pragma unroll
    for (int j = 0; j < 8; j++)
        #pragma unroll
        for (int c = 0; c < 4; c++) acc[j][c] = 0.0f;

    for (int kc = 0; kc < CDIM; kc += 64) {
        // x tile [128][64]: LDG + RNA round + STS
        #pragma unroll
        for (int rep = 0; rep < 8; rep++) {
            int e = tid + rep * 256;
            int r = e >> 4, c4 = (e & 15) * 4;
            float4 v = *(const float4*)(x + (m0 + r) * CDIM + kc + c4);
            v.x = f2tff(v.x); v.y = f2tff(v.y); v.z = f2tff(v.z); v.w = f2tff(v.w);
            *(float4*)&Xs[r * PPITCH + c4] = v;
        }
        // W tile [64k][64n] -> Ws[n][k], RNA rounded
        #pragma unroll
        for (int rep = 0; rep < 4; rep++) {
            int e = tid + rep * 256;
            int r = e >> 4, c4 = (e & 15) * 4;
            float4 v = *(const float4*)(W + (size_t)(kc + r) * HDIM + c4);
            Ws[(c4 + 0) * PPITCH + r] = f2tff(v.x);
            Ws[(c4 + 1) * PPITCH + r] = f2tff(v.y);
            Ws[(c4 + 2) * PPITCH + r] = f2tff(v.z);
            Ws[(c4 + 3) * PPITCH + r] = f2tff(v.w);
        }
        __syncthreads();

        #pragma unroll
        for (int ks = 0; ks < 8; ks++) {
            const int kk = ks * 8;
            unsigned a0, a1, a2, a3;
            ldsm4(a0, a1, a2, a3, Xs + mw * PPITCH + kk + idxA);
            #pragma unroll
            for (int j0 = 0; j0 < 8; j0 += 2) {
                unsigned b00, b10, b01, b11;
                ldsm4(b00, b10, b01, b11, Ws + j0 * 8 * PPITCH + kk + idxB);
                mma_tf32(acc[j0],     a0, a1, a2, a3, b00, b10);
                mma_tf32(acc[j0 + 1], a0, a1, a2, a3, b01, b11);
            }
        }
        __syncthreads();
    }

    const int g = lane >> 2, t = lane & 3;
    if (blockIdx.y < 2) {
        float* out = (blockIdx.y == 0) ? g_q : g_k;
        #pragma unroll
        for (int j = 0; j < 8; j++) {
            *(float2*)(out + (m0 + mw + g)     * HDIM + j * 8 + 2 * t) =
                make_float2(f2tff(acc[j][0] * oscale), f2tff(acc[j][1] * oscale));
            *(float2*)(out + (m0 + mw + g + 8) * HDIM + j * 8 + 2 * t) =
                make_float2(f2tff(acc[j][2] * oscale), f2tff(acc[j][3] * oscale));
        }
    } else {
        // V transposed: g_v[(b*64 + h) * 2048 + s]
        const int bb = (int)(m0 >> 11);
        const int s0 = ((int)m0 & 2047) + mw + g;
        #pragma unroll
        for (int j = 0; j < 8; j++) {
            int col = j * 8 + 2 * t;
            g_v[((size_t)bb * 64 + col)     * TSEQ + s0]     = f2tff(acc[j][0]);
            g_v[((size_t)bb * 64 + col + 1) * TSEQ + s0]     = f2tff(acc[j][1]);
            g_v[((size_t)bb * 64 + col)     * TSEQ + s0 + 8] = f2tff(acc[j][2]);
            g_v[((size_t)bb * 64 + col + 1) * TSEQ + s0 + 8] = f2tff(acc[j][3]);
        }
    }
}

// ---------------------------------------------------------------------------
// Kernel 2: causal flash attention. 64x64 tiles, 128 threads / 4 warps.
// cp.async double-buffered K/V, ldmatrix fragment loads, Q frags in regs,
// exp2-domain softmax. Smem: 2 stages x (K+V) + P staging = 87040 B.
// ---------------------------------------------------------------------------
#define APITCH 68
#define TILE_F (64 * APITCH)

__global__ __launch_bounds__(128) void attn_kernel(float* __restrict__ out)
{
    extern __shared__ float sm[];
    float* Ps = sm + 4 * TILE_F;       // [64][APITCH] : Q tile, then P staging

    const int tid  = threadIdx.x;
    const int w    = tid >> 5;
    const int lane = tid & 31;
    const int g    = lane >> 2;
    const int t    = lane & 3;
    const int b    = blockIdx.y;
    const int qt   = gridDim.x - 1 - blockIdx.x;   // heavy tiles first
    const int mw   = w * 16;
    const int lrow = lane & 7;

    const int idxA = ((((lane >> 3) & 1) * 8 + lrow)) * APITCH + ((lane >> 4) & 1) * 4;
    const int idxB = ((((lane >> 4) & 1) * 8 + lrow)) * APITCH + ((lane >> 3) & 1) * 4;

    const float* kb = g_k + (size_t)b * TSEQ * HDIM;   // [s][h]
    const float* vb = g_v + (size_t)b * HDIM * TSEQ;   // [h][s]

    // ---- prologue: Q tile via cp.async into Ps, frags to registers ----
    {
        const float* qb = g_q + ((size_t)b * TSEQ + qt * 64) * HDIM;
        #pragma unroll
        for (int rep = 0; rep < 8; rep++) {
            int e = tid + rep * 128;
            int r = e >> 4, c4 = (e & 15) * 4;
            cpasync16(&Ps[r * APITCH + c4], qb + r * HDIM + c4);
        }
    }
    CP_COMMIT();

    // prefetch tile 0
    {
        #pragma unroll
        for (int rep = 0; rep < 8; rep++) {
            int e = tid + rep * 128;
            int r = e >> 4, c4 = (e & 15) * 4;
            cpasync16(&sm[r * APITCH + c4],          kb + r * HDIM + c4);
            cpasync16(&sm[TILE_F + r * APITCH + c4], vb + r * TSEQ + c4);
        }
    }
    CP_COMMIT();

    cp_wait<1>();       // Q group done (tile 0 may still be in flight)
    __syncthreads();

    unsigned qa[8][4];
    #pragma unroll
    for (int ks = 0; ks < 8; ks++)
        ldsm4(qa[ks][0], qa[ks][1], qa[ks][2], qa[ks][3],
              Ps + mw * APITCH + ks * 8 + idxA);

    float m_i[2] = {-1e30f, -1e30f};
    float l_i[2] = {0.0f, 0.0f};
    float o[8][4];
    #pragma unroll
    for (int j = 0; j < 8; j++)
        #pragma unroll
        for (int c = 0; c < 4; c++) o[j][c] = 0.0f;

    for (int kt = 0; kt <= qt; kt++) {
        const int stg = kt & 1;
        // prefetch next tile into the other stage
        if (kt < qt) {
            const float* kp = kb + (size_t)(kt + 1) * 64 * HDIM;
            const float* vp = vb + (kt + 1) * 64;
            float* Kd = sm + (stg ^ 1) * 2 * TILE_F;
            #pragma unroll
            for (int rep = 0; rep < 8; rep++) {
                int e = tid + rep * 128;
                int r = e >> 4, c4 = (e & 15) * 4;
                cpasync16(&Kd[r * APITCH + c4],          kp + r * HDIM + c4);
                cpasync16(&Kd[TILE_F + r * APITCH + c4], vp + r * TSEQ + c4);
            }
        }
        CP_COMMIT();
        cp_wait<1>();        // current tile (kt) complete
        __syncthreads();

        const float* Ks = sm + stg * 2 * TILE_F;
        const float* Vs = Ks + TILE_F;

        // ---- S = Q K^T ----
        float s[8][4];
        #pragma unroll
        for (int j = 0; j < 8; j++)
            #pragma unroll
            for (int c = 0; c < 4; c++) s[j][c] = 0.0f;

        #pragma unroll
        for (int ks = 0; ks < 8; ks++) {
            const int kk = ks * 8;
            #pragma unroll
            for (int j0 = 0; j0 < 8; j0 += 2) {
                unsigned b00, b10, b01, b11;
                ldsm4(b00, b10, b01, b11, Ks + j0 * 8 * APITCH + kk + idxB);
                mma_tf32(s[j0],     qa[ks][0], qa[ks][1], qa[ks][2], qa[ks][3], b00, b10);
                mma_tf32(s[j0 + 1], qa[ks][0], qa[ks][1], qa[ks][2], qa[ks][3], b01, b11);
            }
        }

        // causal mask on diagonal tile
        if (kt == qt) {
            #pragma unroll
            for (int j = 0; j < 8; j++)
                #pragma unroll
                for (int c = 0; c < 4; c++) {
                    int col = j * 8 + 2 * t + (c & 1);
                    int row = mw + g + ((c >> 1) << 3);
                    if (col > row) s[j][c] = -1e30f;
                }
        }

        // ---- online softmax (exp2 domain) ----
        #pragma unroll
        for (int h = 0; h < 2; h++) {
            const int c0 = h * 2, c1 = h * 2 + 1;
            float mx = -1e30f;
            #pragma unroll
            for (int j = 0; j < 8; j++)
                mx = fmaxf(mx, fmaxf(s[j][c0], s[j][c1]));
            mx = fmaxf(mx, __shfl_xor_sync(0xffffffffu, mx, 1));
            mx = fmaxf(mx, __shfl_xor_sync(0xffffffffu, mx, 2));
            float mnew = fmaxf(m_i[h], mx);
            float alpha = exp2f(m_i[h] - mnew);
            float rs = 0.0f;
            #pragma unroll
            for (int j = 0; j < 8; j++) {
                s[j][c0] = exp2f(s[j][c0] - mnew);
                s[j][c1] = exp2f(s[j][c1] - mnew);
                rs += s[j][c0] + s[j][c1];
            }
            rs += __shfl_xor_sync(0xffffffffu, rs, 1);
            rs += __shfl_xor_sync(0xffffffffu, rs, 2);
            l_i[h] = l_i[h] * alpha + rs;
            m_i[h] = mnew;
            #pragma unroll
            for (int j = 0; j < 8; j++) { o[j][c0] *= alpha; o[j][c1] *= alpha; }
        }

        // ---- stage P (tf32-rounded) into this warp's rows of Ps ----
        #pragma unroll
        for (int j = 0; j < 8; j++) {
            *(float2*)&Ps[(mw + g)     * APITCH + j * 8 + 2 * t] =
                make_float2(f2tff(s[j][0]), f2tff(s[j][1]));
            *(float2*)&Ps[(mw + g + 8) * APITCH + j * 8 + 2 * t] =
                make_float2(f2tff(s[j][2]), f2tff(s[j][3]));
        }
        __syncwarp();

        // ---- O += P V ----
        #pragma unroll
        for (int ks = 0; ks < 8; ks++) {
            const int kk = ks * 8;
            unsigned a0, a1, a2, a3;
            ldsm4(a0, a1, a2, a3, Ps + mw * APITCH + kk + idxA);
            #pragma unroll
            for (int j0 = 0; j0 < 8; j0 += 2) {
                unsigned b00, b10, b01, b11;
                ldsm4(b00, b10, b01, b11, Vs + j0 * 8 * APITCH + kk + idxB);
                mma_tf32(o[j0],     a0, a1, a2, a3, b00, b10);
                mma_tf32(o[j0 + 1], a0, a1, a2, a3, b01, b11);
            }
        }
        __syncthreads();   // all warps done with this stage's K/V + Ps
    }

    // ---- normalize + store ----
    float* ob = out + ((size_t)b * TSEQ + qt * 64) * HDIM;
    float inv0 = 1.0f / l_i[0];
    float inv1 = 1.0f / l_i[1];
    #pragma unroll
    for (int j = 0; j < 8; j++) {
        *(float2*)(ob + (mw + g)     * HDIM + j * 8 + 2 * t) =
            make_float2(o[j][0] * inv0, o[j][1] * inv0);
        *(float2*)(ob + (mw + g + 8) * HDIM + j * 8 + 2 * t) =
            make_float2(o[j][2] * inv1, o[j][3] * inv1);
    }
}

// ---------------------------------------------------------------------------
extern "C" void kernel_launch(void* const* d_in, const int* in_sizes, int n_in,
                              void* d_out, int out_size)
{
    (void)in_sizes; (void)n_in; (void)out_size;
    const float* x  = (const float*)d_in[0];
    const float* Wq = (const float*)d_in[1];
    const float* Wk = (const float*)d_in[2];
    const float* Wv = (const float*)d_in[3];
    float* out = (float*)d_out;

    const int attn_smem = 5 * TILE_F * (int)sizeof(float);   // 87040
    cudaFuncSetAttribute(attn_kernel, cudaFuncAttributeMaxDynamicSharedMemorySize,
                         attn_smem);

    dim3 gproj(BT_TOTAL / 128, 3);
    qkv_proj<<<gproj, 256>>>(x, Wq, Wk, Wv);

    dim3 gattn(TSEQ / 64, BATCH);
    attn_kernel<<<gattn, 128, attn_smem>>>(out);
}

// round 5
// speedup vs baseline: 3.5138x; 1.1465x over previous
#include <cuda_runtime.h>

#define BATCH 8
#define TSEQ 2048
#define CDIM 768
#define HDIM 64
#define BT_TOTAL (BATCH*TSEQ)
#define NSPLIT 2

// Projected Q, K (natural [b][s][h]) and V (TRANSPOSED [b][h][s]).
// All values already tf32-RNA-rounded; Q pre-scaled by 0.125*log2(e).
__device__ float g_q[BT_TOTAL*HDIM];
__device__ float g_k[BT_TOTAL*HDIM];
__device__ float g_v[BT_TOTAL*HDIM];
// split-K partials
__device__ float g_po[NSPLIT*BT_TOTAL*HDIM];   // unnormalized O
__device__ float g_pm[NSPLIT*BT_TOTAL];        // row max (exp2 domain)
__device__ float g_pl[NSPLIT*BT_TOTAL];        // row sum

// ---------------------------------------------------------------------------
__device__ __forceinline__ unsigned f2tf(float f) {
    unsigned u;
    asm("cvt.rna.tf32.f32 %0, %1;" : "=r"(u) : "f"(f));
    return u;
}
__device__ __forceinline__ float f2tff(float f) { return __uint_as_float(f2tf(f)); }

__device__ __forceinline__ void mma_tf32(float c[4],
                                         unsigned a0, unsigned a1, unsigned a2, unsigned a3,
                                         unsigned b0, unsigned b1) {
    asm volatile(
        "mma.sync.aligned.m16n8k8.row.col.f32.tf32.tf32.f32 "
        "{%0,%1,%2,%3},{%4,%5,%6,%7},{%8,%9},{%0,%1,%2,%3};"
        : "+f"(c[0]), "+f"(c[1]), "+f"(c[2]), "+f"(c[3])
        : "r"(a0), "r"(a1), "r"(a2), "r"(a3), "r"(b0), "r"(b1));
}

__device__ __forceinline__ void ldsm4(unsigned &r0, unsigned &r1, unsigned &r2, unsigned &r3,
                                      const float* p) {
    unsigned a = (unsigned)__cvta_generic_to_shared(p);
    asm volatile("ldmatrix.sync.aligned.m8n8.x4.shared.b16 {%0,%1,%2,%3}, [%4];"
                 : "=r"(r0), "=r"(r1), "=r"(r2), "=r"(r3) : "r"(a));
}

__device__ __forceinline__ void cpasync16(float* dst, const float* src) {
    unsigned a = (unsigned)__cvta_generic_to_shared(dst);
    asm volatile("cp.async.cg.shared.global [%0], [%1], 16;" :: "r"(a), "l"(src));
}
#define CP_COMMIT() asm volatile("cp.async.commit_group;")
template<int N> __device__ __forceinline__ void cp_wait() {
    asm volatile("cp.async.wait_group %0;" :: "n"(N));
}

// ---------------------------------------------------------------------------
// Kernel 1: FUSED QKV projection.  [16384,768] @ [768, 3*64], x read ONCE.
// Grid 256 (M=64 tiles), 256 threads / 8 warps: warp = (wq: m16 rows) x
// (wn: 96-col n-half of the 192 fused outputs). K-chunk 64.
// ---------------------------------------------------------------------------
#define PPITCH 68

__global__ __launch_bounds__(256) void qkv_proj(const float* __restrict__ x,
                                                const float* __restrict__ Wq,
                                                const float* __restrict__ Wk,
                                                const float* __restrict__ Wv)
{
    extern __shared__ float psm[];
    float* Xs = psm;                 // [64][PPITCH]   [m][k]
    float* Ws = psm + 64 * PPITCH;   // [192][PPITCH]  [n][k] (n = 64*mat + h)

    const int tid  = threadIdx.x;
    const int w    = tid >> 5;
    const int lane = tid & 31;
    const int wq   = w & 3;
    const int wn   = w >> 2;
    const int mw   = wq * 16;
    const int lrow = lane & 7;

    const int idxA = ((((lane >> 3) & 1) * 8 + lrow)) * PPITCH + ((lane >> 4) & 1) * 4;
    const int idxB = ((((lane >> 4) & 1) * 8 + lrow)) * PPITCH + ((lane >> 3) & 1) * 4;

    const size_t m0 = (size_t)blockIdx.x * 64;
    const float* Wmat[3] = {Wq, Wk, Wv};

    float acc[12][4];
    #pragma unroll
    for (int j = 0; j < 12; j++)
        #pragma unroll
        for (int c = 0; c < 4; c++) acc[j][c] = 0.0f;

    for (int kc = 0; kc < CDIM; kc += 64) {
        // x tile [64][64]
        #pragma unroll
        for (int rep = 0; rep < 4; rep++) {
            int e = tid + rep * 256;
            int r = e >> 4, c4 = (e & 15) * 4;
            float4 v = *(const float4*)(x + (m0 + r) * CDIM + kc + c4);
            v.x = f2tff(v.x); v.y = f2tff(v.y); v.z = f2tff(v.z); v.w = f2tff(v.w);
            *(float4*)&Xs[r * PPITCH + c4] = v;
        }
        // W tiles: [64k][64n] x 3 -> Ws[n][k]
        #pragma unroll
        for (int mat = 0; mat < 3; mat++) {
            #pragma unroll
            for (int rep = 0; rep < 4; rep++) {
                int e = tid + rep * 256;
                int r = e >> 4, c4 = (e & 15) * 4;
                float4 v = *(const float4*)(Wmat[mat] + (size_t)(kc + r) * HDIM + c4);
                Ws[(mat * 64 + c4 + 0) * PPITCH + r] = f2tff(v.x);
                Ws[(mat * 64 + c4 + 1) * PPITCH + r] = f2tff(v.y);
                Ws[(mat * 64 + c4 + 2) * PPITCH + r] = f2tff(v.z);
                Ws[(mat * 64 + c4 + 3) * PPITCH + r] = f2tff(v.w);
            }
        }
        __syncthreads();

        #pragma unroll
        for (int ks = 0; ks < 8; ks++) {
            const int kk = ks * 8;
            unsigned a0, a1, a2, a3;
            ldsm4(a0, a1, a2, a3, Xs + mw * PPITCH + kk + idxA);
            #pragma unroll
            for (int j0 = 0; j0 < 12; j0 += 2) {
                unsigned b00, b10, b01, b11;
                ldsm4(b00, b10, b01, b11,
                      Ws + (wn * 96 + j0 * 8) * PPITCH + kk + idxB);
                mma_tf32(acc[j0],     a0, a1, a2, a3, b00, b10);
                mma_tf32(acc[j0 + 1], a0, a1, a2, a3, b01, b11);
            }
        }
        __syncthreads();
    }

    const int g = lane >> 2, t = lane & 3;
    const float qscale = 0.18033688011112042f;   // 0.125 * log2(e)
    const int bb = (int)(m0 >> 11);
    const int s0 = ((int)m0 & 2047) + mw + g;

    #pragma unroll
    for (int j = 0; j < 12; j++) {
        int n   = wn * 96 + j * 8;
        int mat = n >> 6;
        int col = (n & 63) + 2 * t;
        if (mat == 0) {
            *(float2*)(g_q + (m0 + mw + g)     * HDIM + col) =
                make_float2(f2tff(acc[j][0] * qscale), f2tff(acc[j][1] * qscale));
            *(float2*)(g_q + (m0 + mw + g + 8) * HDIM + col) =
                make_float2(f2tff(acc[j][2] * qscale), f2tff(acc[j][3] * qscale));
        } else if (mat == 1) {
            *(float2*)(g_k + (m0 + mw + g)     * HDIM + col) =
                make_float2(f2tff(acc[j][0]), f2tff(acc[j][1]));
            *(float2*)(g_k + (m0 + mw + g + 8) * HDIM + col) =
                make_float2(f2tff(acc[j][2]), f2tff(acc[j][3]));
        } else {
            g_v[((size_t)bb * 64 + col)     * TSEQ + s0]     = f2tff(acc[j][0]);
            g_v[((size_t)bb * 64 + col + 1) * TSEQ + s0]     = f2tff(acc[j][1]);
            g_v[((size_t)bb * 64 + col)     * TSEQ + s0 + 8] = f2tff(acc[j][2]);
            g_v[((size_t)bb * 64 + col + 1) * TSEQ + s0 + 8] = f2tff(acc[j][3]);
        }
    }
}

// ---------------------------------------------------------------------------
// Kernel 2: split-K causal flash attention partials. Grid (64, 8):
// blockIdx.x -> (qt, split). Split s owns kv tiles [s? half:0 , s? nkv:half).
// Writes unnormalized O + (m, l) per row to scratch.
// ---------------------------------------------------------------------------
#define APITCH 68
#define TILE_F (64 * APITCH)

__global__ __launch_bounds__(128) void attn_part(int dummy)
{
    extern __shared__ float sm[];
    float* Ps = sm + 4 * TILE_F;

    const int tid  = threadIdx.x;
    const int w    = tid >> 5;
    const int lane = tid & 31;
    const int g    = lane >> 2;
    const int t    = lane & 3;
    const int b    = blockIdx.y;
    const int qt    = 31 - (blockIdx.x >> 1);    // heavy q-tiles first
    const int split = blockIdx.x & 1;
    const int mw   = w * 16;
    const int lrow = lane & 7;

    const int nkv  = qt + 1;
    const int half = nkv >> 1;
    const int kt0  = split ? half : 0;
    const int kt1  = split ? nkv  : half;

    const size_t rbase = (size_t)split * BT_TOTAL + (size_t)b * TSEQ + qt * 64;

    if (kt0 == kt1) {
        // empty split: zero partials
        for (int e = tid; e < 64 * HDIM; e += 128)
            g_po[(rbase + (e >> 6)) * HDIM + (e & 63)] = 0.0f;
        for (int r = tid; r < 64; r += 128) {
            g_pm[rbase + r] = -1e30f;
            g_pl[rbase + r] = 0.0f;
        }
        return;
    }

    const int idxA = ((((lane >> 3) & 1) * 8 + lrow)) * APITCH + ((lane >> 4) & 1) * 4;
    const int idxB = ((((lane >> 4) & 1) * 8 + lrow)) * APITCH + ((lane >> 3) & 1) * 4;

    const float* kb = g_k + (size_t)b * TSEQ * HDIM;   // [s][h]
    const float* vb = g_v + (size_t)b * HDIM * TSEQ;   // [h][s]

    // prologue: Q tile + first kv tile
    {
        const float* qb = g_q + ((size_t)b * TSEQ + qt * 64) * HDIM;
        #pragma unroll
        for (int rep = 0; rep < 8; rep++) {
            int e = tid + rep * 128;
            int r = e >> 4, c4 = (e & 15) * 4;
            cpasync16(&Ps[r * APITCH + c4], qb + r * HDIM + c4);
        }
    }
    CP_COMMIT();
    {
        const float* kp = kb + (size_t)kt0 * 64 * HDIM;
        const float* vp = vb + kt0 * 64;
        float* Kd = sm + (kt0 & 1) * 2 * TILE_F;
        #pragma unroll
        for (int rep = 0; rep < 8; rep++) {
            int e = tid + rep * 128;
            int r = e >> 4, c4 = (e & 15) * 4;
            cpasync16(&Kd[r * APITCH + c4],          kp + r * HDIM + c4);
            cpasync16(&Kd[TILE_F + r * APITCH + c4], vp + r * TSEQ + c4);
        }
    }
    CP_COMMIT();
    cp_wait<1>();
    __syncthreads();

    unsigned qa[8][4];
    #pragma unroll
    for (int ks = 0; ks < 8; ks++)
        ldsm4(qa[ks][0], qa[ks][1], qa[ks][2], qa[ks][3],
              Ps + mw * APITCH + ks * 8 + idxA);

    float m_i[2] = {-1e30f, -1e30f};
    float l_i[2] = {0.0f, 0.0f};
    float o[8][4];
    #pragma unroll
    for (int j = 0; j < 8; j++)
        #pragma unroll
        for (int c = 0; c < 4; c++) o[j][c] = 0.0f;

    for (int kt = kt0; kt < kt1; kt++) {
        const int stg = kt & 1;
        if (kt + 1 < kt1) {
            const float* kp = kb + (size_t)(kt + 1) * 64 * HDIM;
            const float* vp = vb + (kt + 1) * 64;
            float* Kd = sm + (stg ^ 1) * 2 * TILE_F;
            #pragma unroll
            for (int rep = 0; rep < 8; rep++) {
                int e = tid + rep * 128;
                int r = e >> 4, c4 = (e & 15) * 4;
                cpasync16(&Kd[r * APITCH + c4],          kp + r * HDIM + c4);
                cpasync16(&Kd[TILE_F + r * APITCH + c4], vp + r * TSEQ + c4);
            }
        }
        CP_COMMIT();
        cp_wait<1>();
        __syncthreads();

        const float* Ks = sm + stg * 2 * TILE_F;
        const float* Vs = Ks + TILE_F;

        float s[8][4];
        #pragma unroll
        for (int j = 0; j < 8; j++)
            #pragma unroll
            for (int c = 0; c < 4; c++) s[j][c] = 0.0f;

        #pragma unroll
        for (int ks = 0; ks < 8; ks++) {
            const int kk = ks * 8;
            #pragma unroll
            for (int j0 = 0; j0 < 8; j0 += 2) {
                unsigned b00, b10, b01, b11;
                ldsm4(b00, b10, b01, b11, Ks + j0 * 8 * APITCH + kk + idxB);
                mma_tf32(s[j0],     qa[ks][0], qa[ks][1], qa[ks][2], qa[ks][3], b00, b10);
                mma_tf32(s[j0 + 1], qa[ks][0], qa[ks][1], qa[ks][2], qa[ks][3], b01, b11);
            }
        }

        if (kt == qt) {          // diagonal tile (only in split 1)
            #pragma unroll
            for (int j = 0; j < 8; j++)
                #pragma unroll
                for (int c = 0; c < 4; c++) {
                    int col = j * 8 + 2 * t + (c & 1);
                    int row = mw + g + ((c >> 1) << 3);
                    if (col > row) s[j][c] = -1e30f;
                }
        }

        #pragma unroll
        for (int h = 0; h < 2; h++) {
            const int c0 = h * 2, c1 = h * 2 + 1;
            float mx = -1e30f;
            #pragma unroll
            for (int j = 0; j < 8; j++)
                mx = fmaxf(mx, fmaxf(s[j][c0], s[j][c1]));
            mx = fmaxf(mx, __shfl_xor_sync(0xffffffffu, mx, 1));
            mx = fmaxf(mx, __shfl_xor_sync(0xffffffffu, mx, 2));
            float mnew = fmaxf(m_i[h], mx);
            float alpha = exp2f(m_i[h] - mnew);
            float rs = 0.0f;
            #pragma unroll
            for (int j = 0; j < 8; j++) {
                s[j][c0] = exp2f(s[j][c0] - mnew);
                s[j][c1] = exp2f(s[j][c1] - mnew);
                rs += s[j][c0] + s[j][c1];
            }
            rs += __shfl_xor_sync(0xffffffffu, rs, 1);
            rs += __shfl_xor_sync(0xffffffffu, rs, 2);
            l_i[h] = l_i[h] * alpha + rs;
            m_i[h] = mnew;
            #pragma unroll
            for (int j = 0; j < 8; j++) { o[j][c0] *= alpha; o[j][c1] *= alpha; }
        }

        #pragma unroll
        for (int j = 0; j < 8; j++) {
            *(float2*)&Ps[(mw + g)     * APITCH + j * 8 + 2 * t] =
                make_float2(f2tff(s[j][0]), f2tff(s[j][1]));
            *(float2*)&Ps[(mw + g + 8) * APITCH + j * 8 + 2 * t] =
                make_float2(f2tff(s[j][2]), f2tff(s[j][3]));
        }
        __syncwarp();

        #pragma unroll
        for (int ks = 0; ks < 8; ks++) {
            const int kk = ks * 8;
            unsigned a0, a1, a2, a3;
            ldsm4(a0, a1, a2, a3, Ps + mw * APITCH + kk + idxA);
            #pragma unroll
            for (int j0 = 0; j0 < 8; j0 += 2) {
                unsigned b00, b10, b01, b11;
                ldsm4(b00, b10, b01, b11, Vs + j0 * 8 * APITCH + kk + idxB);
                mma_tf32(o[j0],     a0, a1, a2, a3, b00, b10);
                mma_tf32(o[j0 + 1], a0, a1, a2, a3, b01, b11);
            }
        }
        __syncthreads();
    }

    // store partials (unnormalized O, m, l)
    float* po = g_po + rbase * HDIM;
    #pragma unroll
    for (int j = 0; j < 8; j++) {
        *(float2*)(po + (mw + g)     * HDIM + j * 8 + 2 * t) = make_float2(o[j][0], o[j][1]);
        *(float2*)(po + (mw + g + 8) * HDIM + j * 8 + 2 * t) = make_float2(o[j][2], o[j][3]);
    }
    if (t == 0) {
        g_pm[rbase + mw + g]     = m_i[0];
        g_pl[rbase + mw + g]     = l_i[0];
        g_pm[rbase + mw + g + 8] = m_i[1];
        g_pl[rbase + mw + g + 8] = l_i[1];
    }
}

// ---------------------------------------------------------------------------
// Kernel 3: combine the two splits.  out = (O0*w0 + O1*w1) / (l0*w0 + l1*w1)
// ---------------------------------------------------------------------------
__global__ __launch_bounds__(256) void attn_combine(float* __restrict__ out)
{
    int idx = blockIdx.x * 256 + threadIdx.x;     // over 16384*64
    int r = idx >> 6;
    float m0 = g_pm[r], m1 = g_pm[BT_TOTAL + r];
    float M  = fmaxf(m0, m1);
    float w0 = exp2f(m0 - M), w1 = exp2f(m1 - M);
    float l  = g_pl[r] * w0 + g_pl[BT_TOTAL + r] * w1;
    float v  = g_po[idx] * w0 + g_po[(size_t)BT_TOTAL * HDIM + idx] * w1;
    out[idx] = v / l;
}

// ---------------------------------------------------------------------------
extern "C" void kernel_launch(void* const* d_in, const int* in_sizes, int n_in,
                              void* d_out, int out_size)
{
    (void)in_sizes; (void)n_in; (void)out_size;
    const float* x  = (const float*)d_in[0];
    const float* Wq = (const float*)d_in[1];
    const float* Wk = (const float*)d_in[2];
    const float* Wv = (const float*)d_in[3];
    float* out = (float*)d_out;

    const int proj_smem = (64 + 192) * PPITCH * (int)sizeof(float);  // 69632
    cudaFuncSetAttribute(qkv_proj, cudaFuncAttributeMaxDynamicSharedMemorySize,
                         proj_smem);
    const int attn_smem = 5 * TILE_F * (int)sizeof(float);           // 87040
    cudaFuncSetAttribute(attn_part, cudaFuncAttributeMaxDynamicSharedMemorySize,
                         attn_smem);

    qkv_proj<<<BT_TOTAL / 64, 256, proj_smem>>>(x, Wq, Wk, Wv);

    dim3 gattn(2 * TSEQ / 64, BATCH);
    attn_part<<<gattn, 128, attn_smem>>>(0);

    attn_combine<<<BT_TOTAL * HDIM / 256, 256>>>(out);
}

// round 7
// speedup vs baseline: 4.4146x; 1.2564x over previous
#include <cuda_runtime.h>

#define BATCH 8
#define TSEQ 2048
#define CDIM 768
#define HDIM 64
#define BT_TOTAL (BATCH*TSEQ)
#define NSPLIT 2

// Projected Q, K (natural [b][s][h]) and V (TRANSPOSED [b][h][s]).
// All values already tf32-RNA-rounded; Q pre-scaled by 0.125*log2(e).
__device__ float g_q[BT_TOTAL*HDIM];
__device__ float g_k[BT_TOTAL*HDIM];
__device__ float g_v[BT_TOTAL*HDIM];
// split-K partials
__device__ float g_po[NSPLIT*BT_TOTAL*HDIM];
__device__ float g_pm[NSPLIT*BT_TOTAL];
__device__ float g_pl[NSPLIT*BT_TOTAL];

// ---------------------------------------------------------------------------
__device__ __forceinline__ unsigned f2tf(float f) {
    unsigned u;
    asm("cvt.rna.tf32.f32 %0, %1;" : "=r"(u) : "f"(f));
    return u;
}
__device__ __forceinline__ float f2tff(float f) { return __uint_as_float(f2tf(f)); }

__device__ __forceinline__ void mma_tf32(float c[4],
                                         unsigned a0, unsigned a1, unsigned a2, unsigned a3,
                                         unsigned b0, unsigned b1) {
    asm volatile(
        "mma.sync.aligned.m16n8k8.row.col.f32.tf32.tf32.f32 "
        "{%0,%1,%2,%3},{%4,%5,%6,%7},{%8,%9},{%0,%1,%2,%3};"
        : "+f"(c[0]), "+f"(c[1]), "+f"(c[2]), "+f"(c[3])
        : "r"(a0), "r"(a1), "r"(a2), "r"(a3), "r"(b0), "r"(b1));
}

__device__ __forceinline__ void ldsm4(unsigned &r0, unsigned &r1, unsigned &r2, unsigned &r3,
                                      const float* p) {
    unsigned a = (unsigned)__cvta_generic_to_shared(p);
    asm volatile("ldmatrix.sync.aligned.m8n8.x4.shared.b16 {%0,%1,%2,%3}, [%4];"
                 : "=r"(r0), "=r"(r1), "=r"(r2), "=r"(r3) : "r"(a));
}

__device__ __forceinline__ void cpasync16(float* dst, const float* src) {
    unsigned a = (unsigned)__cvta_generic_to_shared(dst);
    asm volatile("cp.async.cg.shared.global [%0], [%1], 16;" :: "r"(a), "l"(src));
}
#define CP_COMMIT() asm volatile("cp.async.commit_group;")
template<int N> __device__ __forceinline__ void cp_wait() {
    asm volatile("cp.async.wait_group %0;" :: "n"(N));
}

// ---------------------------------------------------------------------------
// Kernel 1: FUSED QKV projection, software-pipelined.
// [16384,768] @ [768, 192].  Grid 128 (M=128 tiles), 512 threads / 16 warps:
// warp = (wq 0..7: m16 rows) x (wn 0..1: 96-col n-half).  K-chunk 32,
// double-buffered smem; W staged [n][k] pitch 32 with XOR swizzle.
// ---------------------------------------------------------------------------
#define XP 36
#define XS_F (128 * XP)       // 4608 floats per stage
#define WS_F (192 * 32)       // 6144 floats per stage

__global__ __launch_bounds__(512) void qkv_proj(const float* __restrict__ x,
                                                const float* __restrict__ Wq,
                                                const float* __restrict__ Wk,
                                                const float* __restrict__ Wv)
{
    extern __shared__ float psm[];
    float* Xs[2] = { psm,            psm + XS_F };
    float* Ws[2] = { psm + 2*XS_F,   psm + 2*XS_F + WS_F };

    const int tid  = threadIdx.x;
    const int w    = tid >> 5;
    const int lane = tid & 31;
    const int wq   = w & 7;
    const int wn   = w >> 3;
    const int lrow = lane & 7;

    // A-side ldmatrix lane pattern (pitch XP)
    const int idxA = (((lane >> 3) & 1) * 8 + lrow) * XP + ((lane >> 4) & 1) * 4;
    // B-side swizzled components
    const int nr = ((lane >> 4) & 1) * 8 + lrow;   // n row within 16-row pair
    const int kb = ((lane >> 3) & 1) * 4;          // k 4-group select
    const int xrs = lrow << 2;                     // xor swizzle term

    const size_t m0 = (size_t)blockIdx.x * 128;
    const float* Wmat[3] = {Wq, Wk, Wv};

    // x LDG/STS mapping: rep<2, idx = tid + rep*512: r=idx>>3, c4=(idx&7)*4
    const int xr0 = tid >> 3,          xc0 = (tid & 7) * 4;
    const int xr1 = (tid + 512) >> 3,  xc1 = (tid & 7) * 4;
    // W mapping: rep<3 (rep==mat), col = tid&63, kg = tid>>6 (0..7)
    const int wcol = tid & 63;
    const int wkg  = tid >> 6;

    float4 xg[2], wg[3];

    auto ldg_chunk = [&](int kc) {
        xg[0] = *(const float4*)(x + (m0 + xr0) * CDIM + kc + xc0);
        xg[1] = *(const float4*)(x + (m0 + xr1) * CDIM + kc + xc1);
        #pragma unroll
        for (int rep = 0; rep < 3; rep++) {
            const float* Wp = Wmat[rep] + (size_t)(kc + wkg * 4) * HDIM + wcol;
            wg[rep] = make_float4(Wp[0], Wp[64], Wp[128], Wp[192]);
        }
    };
    auto sts_chunk = [&](int s) {
        float4 v0 = xg[0], v1 = xg[1];
        v0.x = f2tff(v0.x); v0.y = f2tff(v0.y); v0.z = f2tff(v0.z); v0.w = f2tff(v0.w);
        v1.x = f2tff(v1.x); v1.y = f2tff(v1.y); v1.z = f2tff(v1.z); v1.w = f2tff(v1.w);
        *(float4*)&Xs[s][xr0 * XP + xc0] = v0;
        *(float4*)&Xs[s][xr1 * XP + xc1] = v1;
        #pragma unroll
        for (int rep = 0; rep < 3; rep++) {
            int n = rep * 64 + wcol;
            float4 v = wg[rep];
            v.x = f2tff(v.x); v.y = f2tff(v.y); v.z = f2tff(v.z); v.w = f2tff(v.w);
            *(float4*)&Ws[s][n * 32 + ((wkg * 4) ^ ((n & 7) << 2))] = v;
        }
    };

    float acc[12][4];
    #pragma unroll
    for (int j = 0; j < 12; j++)
        #pragma unroll
        for (int c = 0; c < 4; c++) acc[j][c] = 0.0f;

    ldg_chunk(0);
    sts_chunk(0);

    const int NCH = CDIM / 32;   // 24
    for (int ch = 0; ch < NCH; ch++) {
        const int s = ch & 1;
        if (ch + 1 < NCH) ldg_chunk((ch + 1) * 32);
        __syncthreads();

        #pragma unroll
        for (int ks = 0; ks < 4; ks++) {
            const int kk = ks * 8;
            unsigned a0, a1, a2, a3;
            ldsm4(a0, a1, a2, a3, Xs[s] + wq * 16 * XP + kk + idxA);
            const int koff = (kk + kb) ^ xrs;
            #pragma unroll
            for (int j0 = 0; j0 < 12; j0 += 2) {
                unsigned b00, b10, b01, b11;
                ldsm4(b00, b10, b01, b11,
                      Ws[s] + (wn * 96 + j0 * 8 + nr) * 32 + koff);
                mma_tf32(acc[j0],     a0, a1, a2, a3, b00, b10);
                mma_tf32(acc[j0 + 1], a0, a1, a2, a3, b01, b11);
            }
        }
        if (ch + 1 < NCH) sts_chunk(s ^ 1);
    }

    // ---- store ----
    const int g = lane >> 2, t = lane & 3;
    const int mw = wq * 16;
    const float qscale = 0.18033688011112042f;   // 0.125 * log2(e)
    const int bb = (int)(m0 >> 11);
    const int s0 = ((int)m0 & 2047) + mw + g;

    #pragma unroll
    for (int j = 0; j < 12; j++) {
        int n   = wn * 96 + j * 8;
        int mat = n >> 6;
        int col = (n & 63) + 2 * t;
        if (mat == 0) {
            *(float2*)(g_q + (m0 + mw + g)     * HDIM + col) =
                make_float2(f2tff(acc[j][0] * qscale), f2tff(acc[j][1] * qscale));
            *(float2*)(g_q + (m0 + mw + g + 8) * HDIM + col) =
                make_float2(f2tff(acc[j][2] * qscale), f2tff(acc[j][3] * qscale));
        } else if (mat == 1) {
            *(float2*)(g_k + (m0 + mw + g)     * HDIM + col) =
                make_float2(f2tff(acc[j][0]), f2tff(acc[j][1]));
            *(float2*)(g_k + (m0 + mw + g + 8) * HDIM + col) =
                make_float2(f2tff(acc[j][2]), f2tff(acc[j][3]));
        } else {
            g_v[((size_t)bb * 64 + col)     * TSEQ + s0]     = f2tff(acc[j][0]);
            g_v[((size_t)bb * 64 + col + 1) * TSEQ + s0]     = f2tff(acc[j][1]);
            g_v[((size_t)bb * 64 + col)     * TSEQ + s0 + 8] = f2tff(acc[j][2]);
            g_v[((size_t)bb * 64 + col + 1) * TSEQ + s0 + 8] = f2tff(acc[j][3]);
        }
    }
}

// ---------------------------------------------------------------------------
// Kernel 2: split-K causal flash attention partials (unchanged from R5).
// ---------------------------------------------------------------------------
#define APITCH 68
#define TILE_F (64 * APITCH)

__global__ __launch_bounds__(128) void attn_part(int dummy)
{
    extern __shared__ float sm[];
    float* Ps = sm + 4 * TILE_F;

    const int tid  = threadIdx.x;
    const int w    = tid >> 5;
    const int lane = tid & 31;
    const int g    = lane >> 2;
    const int t    = lane & 3;
    const int b    = blockIdx.y;
    const int qt    = 31 - (blockIdx.x >> 1);
    const int split = blockIdx.x & 1;
    const int mw   = w * 16;
    const int lrow = lane & 7;

    const int nkv  = qt + 1;
    const int half = nkv >> 1;
    const int kt0  = split ? half : 0;
    const int kt1  = split ? nkv  : half;

    const size_t rbase = (size_t)split * BT_TOTAL + (size_t)b * TSEQ + qt * 64;

    if (kt0 == kt1) {
        for (int e = tid; e < 64 * HDIM; e += 128)
            g_po[(rbase + (e >> 6)) * HDIM + (e & 63)] = 0.0f;
        for (int r = tid; r < 64; r += 128) {
            g_pm[rbase + r] = -1e30f;
            g_pl[rbase + r] = 0.0f;
        }
        return;
    }

    const int idxA = (((lane >> 3) & 1) * 8 + lrow) * APITCH + ((lane >> 4) & 1) * 4;
    const int idxB = (((lane >> 4) & 1) * 8 + lrow) * APITCH + ((lane >> 3) & 1) * 4;

    const float* kb = g_k + (size_t)b * TSEQ * HDIM;
    const float* vb = g_v + (size_t)b * HDIM * TSEQ;

    {
        const float* qb = g_q + ((size_t)b * TSEQ + qt * 64) * HDIM;
        #pragma unroll
        for (int rep = 0; rep < 8; rep++) {
            int e = tid + rep * 128;
            int r = e >> 4, c4 = (e & 15) * 4;
            cpasync16(&Ps[r * APITCH + c4], qb + r * HDIM + c4);
        }
    }
    CP_COMMIT();
    {
        const float* kp = kb + (size_t)kt0 * 64 * HDIM;
        const float* vp = vb + kt0 * 64;
        float* Kd = sm + (kt0 & 1) * 2 * TILE_F;
        #pragma unroll
        for (int rep = 0; rep < 8; rep++) {
            int e = tid + rep * 128;
            int r = e >> 4, c4 = (e & 15) * 4;
            cpasync16(&Kd[r * APITCH + c4],          kp + r * HDIM + c4);
            cpasync16(&Kd[TILE_F + r * APITCH + c4], vp + r * TSEQ + c4);
        }
    }
    CP_COMMIT();
    cp_wait<1>();
    __syncthreads();

    unsigned qa[8][4];
    #pragma unroll
    for (int ks = 0; ks < 8; ks++)
        ldsm4(qa[ks][0], qa[ks][1], qa[ks][2], qa[ks][3],
              Ps + mw * APITCH + ks * 8 + idxA);

    float m_i[2] = {-1e30f, -1e30f};
    float l_i[2] = {0.0f, 0.0f};
    float o[8][4];
    #pragma unroll
    for (int j = 0; j < 8; j++)
        #pragma unroll
        for (int c = 0; c < 4; c++) o[j][c] = 0.0f;

    for (int kt = kt0; kt < kt1; kt++) {
        const int stg = kt & 1;
        if (kt + 1 < kt1) {
            const float* kp = kb + (size_t)(kt + 1) * 64 * HDIM;
            const float* vp = vb + (kt + 1) * 64;
            float* Kd = sm + (stg ^ 1) * 2 * TILE_F;
            #pragma unroll
            for (int rep = 0; rep < 8; rep++) {
                int e = tid + rep * 128;
                int r = e >> 4, c4 = (e & 15) * 4;
                cpasync16(&Kd[r * APITCH + c4],          kp + r * HDIM + c4);
                cpasync16(&Kd[TILE_F + r * APITCH + c4], vp + r * TSEQ + c4);
            }
        }
        CP_COMMIT();
        cp_wait<1>();
        __syncthreads();

        const float* Ks = sm + stg * 2 * TILE_F;
        const float* Vs = Ks + TILE_F;

        float s[8][4];
        #pragma unroll
        for (int j = 0; j < 8; j++)
            #pragma unroll
            for (int c = 0; c < 4; c++) s[j][c] = 0.0f;

        #pragma unroll
        for (int ks = 0; ks < 8; ks++) {
            const int kk = ks * 8;
            #pragma unroll
            for (int j0 = 0; j0 < 8; j0 += 2) {
                unsigned b00, b10, b01, b11;
                ldsm4(b00, b10, b01, b11, Ks + j0 * 8 * APITCH + kk + idxB);
                mma_tf32(s[j0],     qa[ks][0], qa[ks][1], qa[ks][2], qa[ks][3], b00, b10);
                mma_tf32(s[j0 + 1], qa[ks][0], qa[ks][1], qa[ks][2], qa[ks][3], b01, b11);
            }
        }

        if (kt == qt) {
            #pragma unroll
            for (int j = 0; j < 8; j++)
                #pragma unroll
                for (int c = 0; c < 4; c++) {
                    int col = j * 8 + 2 * t + (c & 1);
                    int row = mw + g + ((c >> 1) << 3);
                    if (col > row) s[j][c] = -1e30f;
                }
        }

        #pragma unroll
        for (int h = 0; h < 2; h++) {
            const int c0 = h * 2, c1 = h * 2 + 1;
            float mx = -1e30f;
            #pragma unroll
            for (int j = 0; j < 8; j++)
                mx = fmaxf(mx, fmaxf(s[j][c0], s[j][c1]));
            mx = fmaxf(mx, __shfl_xor_sync(0xffffffffu, mx, 1));
            mx = fmaxf(mx, __shfl_xor_sync(0xffffffffu, mx, 2));
            float mnew = fmaxf(m_i[h], mx);
            float alpha = exp2f(m_i[h] - mnew);
            float rs = 0.0f;
            #pragma unroll
            for (int j = 0; j < 8; j++) {
                s[j][c0] = exp2f(s[j][c0] - mnew);
                s[j][c1] = exp2f(s[j][c1] - mnew);
                rs += s[j][c0] + s[j][c1];
            }
            rs += __shfl_xor_sync(0xffffffffu, rs, 1);
            rs += __shfl_xor_sync(0xffffffffu, rs, 2);
            l_i[h] = l_i[h] * alpha + rs;
            m_i[h] = mnew;
            #pragma unroll
            for (int j = 0; j < 8; j++) { o[j][c0] *= alpha; o[j][c1] *= alpha; }
        }

        #pragma unroll
        for (int j = 0; j < 8; j++) {
            *(float2*)&Ps[(mw + g)     * APITCH + j * 8 + 2 * t] =
                make_float2(f2tff(s[j][0]), f2tff(s[j][1]));
            *(float2*)&Ps[(mw + g + 8) * APITCH + j * 8 + 2 * t] =
                make_float2(f2tff(s[j][2]), f2tff(s[j][3]));
        }
        __syncwarp();

        #pragma unroll
        for (int ks = 0; ks < 8; ks++) {
            const int kk = ks * 8;
            unsigned a0, a1, a2, a3;
            ldsm4(a0, a1, a2, a3, Ps + mw * APITCH + kk + idxA);
            #pragma unroll
            for (int j0 = 0; j0 < 8; j0 += 2) {
                unsigned b00, b10, b01, b11;
                ldsm4(b00, b10, b01, b11, Vs + j0 * 8 * APITCH + kk + idxB);
                mma_tf32(o[j0],     a0, a1, a2, a3, b00, b10);
                mma_tf32(o[j0 + 1], a0, a1, a2, a3, b01, b11);
            }
        }
        __syncthreads();
    }

    float* po = g_po + rbase * HDIM;
    #pragma unroll
    for (int j = 0; j < 8; j++) {
        *(float2*)(po + (mw + g)     * HDIM + j * 8 + 2 * t) = make_float2(o[j][0], o[j][1]);
        *(float2*)(po + (mw + g + 8) * HDIM + j * 8 + 2 * t) = make_float2(o[j][2], o[j][3]);
    }
    if (t == 0) {
        g_pm[rbase + mw + g]     = m_i[0];
        g_pl[rbase + mw + g]     = l_i[0];
        g_pm[rbase + mw + g + 8] = m_i[1];
        g_pl[rbase + mw + g + 8] = l_i[1];
    }
}

// ---------------------------------------------------------------------------
// Kernel 3: combine splits.
// ---------------------------------------------------------------------------
__global__ __launch_bounds__(256) void attn_combine(float* __restrict__ out)
{
    int idx = blockIdx.x * 256 + threadIdx.x;
    int r = idx >> 6;
    float m0 = g_pm[r], m1 = g_pm[BT_TOTAL + r];
    float M  = fmaxf(m0, m1);
    float w0 = exp2f(m0 - M), w1 = exp2f(m1 - M);
    float l  = g_pl[r] * w0 + g_pl[BT_TOTAL + r] * w1;
    float v  = g_po[idx] * w0 + g_po[(size_t)BT_TOTAL * HDIM + idx] * w1;
    out[idx] = v / l;
}

// ---------------------------------------------------------------------------
extern "C" void kernel_launch(void* const* d_in, const int* in_sizes, int n_in,
                              void* d_out, int out_size)
{
    (void)in_sizes; (void)n_in; (void)out_size;
    const float* x  = (const float*)d_in[0];
    const float* Wq = (const float*)d_in[1];
    const float* Wk = (const float*)d_in[2];
    const float* Wv = (const float*)d_in[3];
    float* out = (float*)d_out;

    const int proj_smem = 2 * (XS_F + WS_F) * (int)sizeof(float);   // 86016
    cudaFuncSetAttribute(qkv_proj, cudaFuncAttributeMaxDynamicSharedMemorySize,
                         proj_smem);
    const int attn_smem = 5 * TILE_F * (int)sizeof(float);          // 87040
    cudaFuncSetAttribute(attn_part, cudaFuncAttributeMaxDynamicSharedMemorySize,
                         attn_smem);

    qkv_proj<<<BT_TOTAL / 128, 512, proj_smem>>>(x, Wq, Wk, Wv);

    dim3 gattn(2 * TSEQ / 64, BATCH);
    attn_part<<<gattn, 128, attn_smem>>>(0);

    attn_combine<<<BT_TOTAL * HDIM / 256, 256>>>(out);
}

// round 8
// speedup vs baseline: 5.3920x; 1.2214x over previous
#include <cuda_runtime.h>

#define BATCH 8
#define TSEQ 2048
#define CDIM 768
#define HDIM 64
#define BT_TOTAL (BATCH*TSEQ)
#define NSPLIT 2

// Projected Q, K (natural [b][s][h]) and V (TRANSPOSED [b][h][s]).
// All values already tf32-RNA-rounded; Q pre-scaled by 0.125*log2(e).
__device__ float g_q[BT_TOTAL*HDIM];
__device__ float g_k[BT_TOTAL*HDIM];
__device__ float g_v[BT_TOTAL*HDIM];
// split-K partials
__device__ float g_po[NSPLIT*BT_TOTAL*HDIM];
__device__ float g_pm[NSPLIT*BT_TOTAL];
__device__ float g_pl[NSPLIT*BT_TOTAL];

// ---------------------------------------------------------------------------
__device__ __forceinline__ unsigned f2tf(float f) {
    unsigned u;
    asm("cvt.rna.tf32.f32 %0, %1;" : "=r"(u) : "f"(f));
    return u;
}
__device__ __forceinline__ float f2tff(float f) { return __uint_as_float(f2tf(f)); }

__device__ __forceinline__ void mma_tf32(float c[4],
                                         unsigned a0, unsigned a1, unsigned a2, unsigned a3,
                                         unsigned b0, unsigned b1) {
    asm volatile(
        "mma.sync.aligned.m16n8k8.row.col.f32.tf32.tf32.f32 "
        "{%0,%1,%2,%3},{%4,%5,%6,%7},{%8,%9},{%0,%1,%2,%3};"
        : "+f"(c[0]), "+f"(c[1]), "+f"(c[2]), "+f"(c[3])
        : "r"(a0), "r"(a1), "r"(a2), "r"(a3), "r"(b0), "r"(b1));
}

__device__ __forceinline__ void ldsm4(unsigned &r0, unsigned &r1, unsigned &r2, unsigned &r3,
                                      const float* p) {
    unsigned a = (unsigned)__cvta_generic_to_shared(p);
    asm volatile("ldmatrix.sync.aligned.m8n8.x4.shared.b16 {%0,%1,%2,%3}, [%4];"
                 : "=r"(r0), "=r"(r1), "=r"(r2), "=r"(r3) : "r"(a));
}

__device__ __forceinline__ void cpasync16(float* dst, const float* src) {
    unsigned a = (unsigned)__cvta_generic_to_shared(dst);
    asm volatile("cp.async.cg.shared.global [%0], [%1], 16;" :: "r"(a), "l"(src));
}
#define CP_COMMIT() asm volatile("cp.async.commit_group;")
template<int N> __device__ __forceinline__ void cp_wait() {
    asm volatile("cp.async.wait_group %0;" :: "n"(N));
}

// ---------------------------------------------------------------------------
// Kernel 1: FUSED QKV projection, software-pipelined, warp tile m32 x n48.
// CTA tile M=64 x N=192, 256 threads / 8 warps = 2(wq) x 4(wn). Grid 256.
// K-chunk 32, double-buffered smem. W staged [n][k] pitch 32, XOR swizzle.
// ---------------------------------------------------------------------------
#define XP 36
#define XS_F (64 * XP)        // 2304 floats
#define WS_F (192 * 32)       // 6144 floats
#define STG_F (XS_F + WS_F)   // 8448 floats per stage

__global__ __launch_bounds__(256, 2) void qkv_proj(const float* __restrict__ x,
                                                   const float* __restrict__ Wq,
                                                   const float* __restrict__ Wk,
                                                   const float* __restrict__ Wv)
{
    extern __shared__ float psm[];

    const int tid  = threadIdx.x;
    const int w    = tid >> 5;
    const int lane = tid & 31;
    const int wq   = w & 1;
    const int wn   = w >> 1;
    const int mw   = wq * 32;
    const int lrow = lane & 7;

    const int idxA = ((((lane >> 3) & 1) * 8 + lrow)) * XP + ((lane >> 4) & 1) * 4;
    const int nr   = ((lane >> 4) & 1) * 8 + lrow;
    const int kb   = ((lane >> 3) & 1) * 4;
    const int xrs  = lrow << 2;

    const size_t m0 = (size_t)blockIdx.x * 64;
    const float* Wmat[3] = {Wq, Wk, Wv};

    // x staging: 2048 floats, 2 float4/thread
    const int xr0 = tid >> 3,         xc0 = (tid & 7) * 4;
    const int xr1 = (tid + 256) >> 3, xc1 = (tid & 7) * 4;
    // W staging: 6144 floats, 6 float4/thread (scalar gather, stride 64)
    const int wcol = tid & 31;
    const int w8   = tid >> 5;        // k-group 0..7

    float4 xg[2], wg[6];

    auto ldg_chunk = [&](int kc) {
        xg[0] = *(const float4*)(x + (m0 + xr0) * CDIM + kc + xc0);
        xg[1] = *(const float4*)(x + (m0 + xr1) * CDIM + kc + xc1);
        #pragma unroll
        for (int rep = 0; rep < 6; rep++) {
            int n = rep * 32 + wcol;
            const float* Wp = Wmat[n >> 6] + (size_t)(kc + w8 * 4) * HDIM + (n & 63);
            wg[rep] = make_float4(Wp[0], Wp[64], Wp[128], Wp[192]);
        }
    };
    auto sts_chunk = [&](int s) {
        float* Xs = psm + s * STG_F;
        float* Ws = Xs + XS_F;
        float4 v0 = xg[0], v1 = xg[1];
        v0.x = f2tff(v0.x); v0.y = f2tff(v0.y); v0.z = f2tff(v0.z); v0.w = f2tff(v0.w);
        v1.x = f2tff(v1.x); v1.y = f2tff(v1.y); v1.z = f2tff(v1.z); v1.w = f2tff(v1.w);
        *(float4*)&Xs[xr0 * XP + xc0] = v0;
        *(float4*)&Xs[xr1 * XP + xc1] = v1;
        #pragma unroll
        for (int rep = 0; rep < 6; rep++) {
            int n = rep * 32 + wcol;
            float4 v = wg[rep];
            v.x = f2tff(v.x); v.y = f2tff(v.y); v.z = f2tff(v.z); v.w = f2tff(v.w);
            *(float4*)&Ws[n * 32 + ((w8 * 4) ^ ((n & 7) << 2))] = v;
        }
    };

    float acc[2][6][4];
    #pragma unroll
    for (int im = 0; im < 2; im++)
        #pragma unroll
        for (int j = 0; j < 6; j++)
            #pragma unroll
            for (int c = 0; c < 4; c++) acc[im][j][c] = 0.0f;

    ldg_chunk(0);
    sts_chunk(0);

    const int NCH = CDIM / 32;   // 24
    for (int ch = 0; ch < NCH; ch++) {
        const int s = ch & 1;
        if (ch + 1 < NCH) ldg_chunk((ch + 1) * 32);
        __syncthreads();

        const float* Xs = psm + s * STG_F;
        const float* Ws = Xs + XS_F;

        #pragma unroll
        for (int ks = 0; ks < 4; ks++) {
            const int kk = ks * 8;
            unsigned a00, a01, a02, a03, a10, a11, a12, a13;
            ldsm4(a00, a01, a02, a03, Xs + (mw)      * XP + kk + idxA);
            ldsm4(a10, a11, a12, a13, Xs + (mw + 16) * XP + kk + idxA);
            const int koff = (kk + kb) ^ xrs;
            #pragma unroll
            for (int j0 = 0; j0 < 6; j0 += 2) {
                unsigned b00, b10, b01, b11;
                ldsm4(b00, b10, b01, b11,
                      Ws + (wn * 48 + j0 * 8 + nr) * 32 + koff);
                mma_tf32(acc[0][j0],     a00, a01, a02, a03, b00, b10);
                mma_tf32(acc[0][j0 + 1], a00, a01, a02, a03, b01, b11);
                mma_tf32(acc[1][j0],     a10, a11, a12, a13, b00, b10);
                mma_tf32(acc[1][j0 + 1], a10, a11, a12, a13, b01, b11);
            }
        }
        if (ch + 1 < NCH) sts_chunk(s ^ 1);
    }

    // ---- store ----
    const int g = lane >> 2, t = lane & 3;
    const float qscale = 0.18033688011112042f;   // 0.125 * log2(e)
    const int bb = (int)(m0 >> 11);

    #pragma unroll
    for (int im = 0; im < 2; im++) {
        const size_t rb = m0 + mw + im * 16 + g;
        const int s0 = ((int)m0 & 2047) + mw + im * 16 + g;
        #pragma unroll
        for (int j = 0; j < 6; j++) {
            int n   = wn * 48 + j * 8;
            int mat = n >> 6;
            int col = (n & 63) + 2 * t;
            if (mat == 0) {
                *(float2*)(g_q + rb       * HDIM + col) =
                    make_float2(f2tff(acc[im][j][0] * qscale), f2tff(acc[im][j][1] * qscale));
                *(float2*)(g_q + (rb + 8) * HDIM + col) =
                    make_float2(f2tff(acc[im][j][2] * qscale), f2tff(acc[im][j][3] * qscale));
            } else if (mat == 1) {
                *(float2*)(g_k + rb       * HDIM + col) =
                    make_float2(f2tff(acc[im][j][0]), f2tff(acc[im][j][1]));
                *(float2*)(g_k + (rb + 8) * HDIM + col) =
                    make_float2(f2tff(acc[im][j][2]), f2tff(acc[im][j][3]));
            } else {
                g_v[((size_t)bb * 64 + col)     * TSEQ + s0]     = f2tff(acc[im][j][0]);
                g_v[((size_t)bb * 64 + col + 1) * TSEQ + s0]     = f2tff(acc[im][j][1]);
                g_v[((size_t)bb * 64 + col)     * TSEQ + s0 + 8] = f2tff(acc[im][j][2]);
                g_v[((size_t)bb * 64 + col + 1) * TSEQ + s0 + 8] = f2tff(acc[im][j][3]);
            }
        }
    }
}

// ---------------------------------------------------------------------------
// Kernel 2: split-K causal flash attention partials.
// 64KB smem: K double-buffered + V single-buffered (early-issued) + Q/P tile.
// All tiles pitch-64 with XOR swizzle (conflict-free cp.async/ldsm/STS).
// 3 CTAs/SM. Grid (64, 8): blockIdx.x -> (qt, split).
// ---------------------------------------------------------------------------
#define ATF 4096   // floats per 64x64 tile

__global__ __launch_bounds__(128, 3) void attn_part(int dummy)
{
    extern __shared__ float sm[];
    float* Vs  = sm + 2 * ATF;
    float* QPs = sm + 3 * ATF;

    const int tid  = threadIdx.x;
    const int w    = tid >> 5;
    const int lane = tid & 31;
    const int g    = lane >> 2;
    const int t    = lane & 3;
    const int b    = blockIdx.y;
    const int qt    = 31 - (blockIdx.x >> 1);
    const int split = blockIdx.x & 1;
    const int mw   = w * 16;
    const int lrow = lane & 7;

    const int nkv  = qt + 1;
    const int half = nkv >> 1;
    const int kt0  = split ? half : 0;
    const int kt1  = split ? nkv  : half;

    const size_t rbase = (size_t)split * BT_TOTAL + (size_t)b * TSEQ + qt * 64;

    if (kt0 == kt1) {
        for (int e = tid; e < 64 * HDIM; e += 128)
            g_po[(rbase + (e >> 6)) * HDIM + (e & 63)] = 0.0f;
        for (int r = tid; r < 64; r += 128) {
            g_pm[rbase + r] = -1e30f;
            g_pl[rbase + r] = 0.0f;
        }
        return;
    }

    // ldsm lane components (swizzled pitch-64)
    const int arA = ((lane >> 3) & 1) * 8 + lrow;   // A-side row within 16
    const int kaA = ((lane >> 4) & 1) * 4;          // A-side k 4-group
    const int nrB = ((lane >> 4) & 1) * 8 + lrow;   // B-side row within 16
    const int kbB = ((lane >> 3) & 1) * 4;          // B-side k 4-group
    const int xsw = lrow << 2;

    const float* kb = g_k + (size_t)b * TSEQ * HDIM;   // [s][h]
    const float* vb = g_v + (size_t)b * HDIM * TSEQ;   // [h][s]

    auto ld_tile = [&](float* dst, const float* src, int pitch) {
        #pragma unroll
        for (int rep = 0; rep < 8; rep++) {
            int e = tid + rep * 128;
            int r = e >> 4, c4 = (e & 15) * 4;
            cpasync16(&dst[r * 64 + (c4 ^ ((r & 7) << 2))], src + r * pitch + c4);
        }
    };

    // prologue: Q, K(kt0), V(kt0)
    ld_tile(QPs, g_q + ((size_t)b * TSEQ + qt * 64) * HDIM, HDIM);
    CP_COMMIT();
    ld_tile(sm, kb + (size_t)kt0 * 64 * HDIM, HDIM);
    CP_COMMIT();
    ld_tile(Vs, vb + kt0 * 64, TSEQ);
    CP_COMMIT();
    cp_wait<2>();        // Q done
    __syncthreads();

    unsigned qa[8][4];
    #pragma unroll
    for (int ks = 0; ks < 8; ks++)
        ldsm4(qa[ks][0], qa[ks][1], qa[ks][2], qa[ks][3],
              QPs + (mw + arA) * 64 + ((ks * 8 + kaA) ^ xsw));

    float m_i[2] = {-1e30f, -1e30f};
    float l_i[2] = {0.0f, 0.0f};
    float o[8][4];
    #pragma unroll
    for (int j = 0; j < 8; j++)
        #pragma unroll
        for (int c = 0; c < 4; c++) o[j][c] = 0.0f;

    const int niter = kt1 - kt0;
    for (int i = 0; i < niter; i++) {
        const int kt = kt0 + i;
        const int s  = i & 1;
        // prefetch next K into the other stage
        if (i + 1 < niter)
            ld_tile(sm + (s ^ 1) * ATF, kb + (size_t)(kt + 1) * 64 * HDIM, HDIM);
        CP_COMMIT();
        cp_wait<2>();    // K(kt) done
        __syncthreads();

        const float* Ks = sm + s * ATF;

        // ---- S = Q K^T ----
        float sc[8][4];
        #pragma unroll
        for (int j = 0; j < 8; j++)
            #pragma unroll
            for (int c = 0; c < 4; c++) sc[j][c] = 0.0f;

        #pragma unroll
        for (int ks = 0; ks < 8; ks++) {
            const int koff = (ks * 8 + kbB) ^ xsw;
            #pragma unroll
            for (int j0 = 0; j0 < 8; j0 += 2) {
                unsigned b00, b10, b01, b11;
                ldsm4(b00, b10, b01, b11, Ks + (j0 * 8 + nrB) * 64 + koff);
                mma_tf32(sc[j0],     qa[ks][0], qa[ks][1], qa[ks][2], qa[ks][3], b00, b10);
                mma_tf32(sc[j0 + 1], qa[ks][0], qa[ks][1], qa[ks][2], qa[ks][3], b01, b11);
            }
        }

        if (kt == qt) {      // diagonal tile (split 1 only)
            #pragma unroll
            for (int j = 0; j < 8; j++)
                #pragma unroll
                for (int c = 0; c < 4; c++) {
                    int col = j * 8 + 2 * t + (c & 1);
                    int row = mw + g + ((c >> 1) << 3);
                    if (col > row) sc[j][c] = -1e30f;
                }
        }

        // ---- online softmax (exp2 domain) ----
        #pragma unroll
        for (int h = 0; h < 2; h++) {
            const int c0 = h * 2, c1 = h * 2 + 1;
            float mx = -1e30f;
            #pragma unroll
            for (int j = 0; j < 8; j++)
                mx = fmaxf(mx, fmaxf(sc[j][c0], sc[j][c1]));
            mx = fmaxf(mx, __shfl_xor_sync(0xffffffffu, mx, 1));
            mx = fmaxf(mx, __shfl_xor_sync(0xffffffffu, mx, 2));
            float mnew = fmaxf(m_i[h], mx);
            float alpha = exp2f(m_i[h] - mnew);
            float rs = 0.0f;
            #pragma unroll
            for (int j = 0; j < 8; j++) {
                sc[j][c0] = exp2f(sc[j][c0] - mnew);
                sc[j][c1] = exp2f(sc[j][c1] - mnew);
                rs += sc[j][c0] + sc[j][c1];
            }
            rs += __shfl_xor_sync(0xffffffffu, rs, 1);
            rs += __shfl_xor_sync(0xffffffffu, rs, 2);
            l_i[h] = l_i[h] * alpha + rs;
            m_i[h] = mnew;
            #pragma unroll
            for (int j = 0; j < 8; j++) { o[j][c0] *= alpha; o[j][c1] *= alpha; }
        }

        // ---- stage P (tf32-rounded) into this warp's rows of QPs ----
        #pragma unroll
        for (int j = 0; j < 8; j++) {
            const int c   = j * 8 + 2 * t;
            const int cb  = c & ~3;
            const int rem = c & 3;
            *(float2*)&QPs[(mw + g)     * 64 + (cb ^ (g << 2)) + rem] =
                make_float2(f2tff(sc[j][0]), f2tff(sc[j][1]));
            *(float2*)&QPs[(mw + g + 8) * 64 + (cb ^ (g << 2)) + rem] =
                make_float2(f2tff(sc[j][2]), f2tff(sc[j][3]));
        }
        __syncwarp();

        cp_wait<1>();    // V(kt) done
        __syncthreads();

        // ---- O += P V ----
        #pragma unroll
        for (int ks = 0; ks < 8; ks++) {
            const int kk = ks * 8;
            unsigned a0, a1, a2, a3;
            ldsm4(a0, a1, a2, a3, QPs + (mw + arA) * 64 + ((kk + kaA) ^ xsw));
            const int koff = (kk + kbB) ^ xsw;
            #pragma unroll
            for (int j0 = 0; j0 < 8; j0 += 2) {
                unsigned b00, b10, b01, b11;
                ldsm4(b00, b10, b01, b11, Vs + (j0 * 8 + nrB) * 64 + koff);
                mma_tf32(o[j0],     a0, a1, a2, a3, b00, b10);
                mma_tf32(o[j0 + 1], a0, a1, a2, a3, b01, b11);
            }
        }
        __syncthreads();  // all warps done reading Vs before overwrite

        if (i + 1 < niter)
            ld_tile(Vs, vb + (kt + 1) * 64, TSEQ);
        CP_COMMIT();
    }

    // store partials (unnormalized O, m, l)
    float* po = g_po + rbase * HDIM;
    #pragma unroll
    for (int j = 0; j < 8; j++) {
        *(float2*)(po + (mw + g)     * HDIM + j * 8 + 2 * t) = make_float2(o[j][0], o[j][1]);
        *(float2*)(po + (mw + g + 8) * HDIM + j * 8 + 2 * t) = make_float2(o[j][2], o[j][3]);
    }
    if (t == 0) {
        g_pm[rbase + mw + g]     = m_i[0];
        g_pl[rbase + mw + g]     = l_i[0];
        g_pm[rbase + mw + g + 8] = m_i[1];
        g_pl[rbase + mw + g + 8] = l_i[1];
    }
}

// ---------------------------------------------------------------------------
// Kernel 3: combine splits.
// ---------------------------------------------------------------------------
__global__ __launch_bounds__(256) void attn_combine(float* __restrict__ out)
{
    int idx = blockIdx.x * 256 + threadIdx.x;
    int r = idx >> 6;
    float m0 = g_pm[r], m1 = g_pm[BT_TOTAL + r];
    float M  = fmaxf(m0, m1);
    float w0 = exp2f(m0 - M), w1 = exp2f(m1 - M);
    float l  = g_pl[r] * w0 + g_pl[BT_TOTAL + r] * w1;
    float v  = g_po[idx] * w0 + g_po[(size_t)BT_TOTAL * HDIM + idx] * w1;
    out[idx] = v / l;
}

// ---------------------------------------------------------------------------
extern "C" void kernel_launch(void* const* d_in, const int* in_sizes, int n_in,
                              void* d_out, int out_size)
{
    (void)in_sizes; (void)n_in; (void)out_size;
    const float* x  = (const float*)d_in[0];
    const float* Wq = (const float*)d_in[1];
    const float* Wk = (const float*)d_in[2];
    const float* Wv = (const float*)d_in[3];
    float* out = (float*)d_out;

    const int proj_smem = 2 * STG_F * (int)sizeof(float);    // 67584
    cudaFuncSetAttribute(qkv_proj, cudaFuncAttributeMaxDynamicSharedMemorySize,
                         proj_smem);
    const int attn_smem = 4 * ATF * (int)sizeof(float);      // 65536
    cudaFuncSetAttribute(attn_part, cudaFuncAttributeMaxDynamicSharedMemorySize,
                         attn_smem);

    qkv_proj<<<BT_TOTAL / 64, 256, proj_smem>>>(x, Wq, Wk, Wv);

    dim3 gattn(2 * TSEQ / 64, BATCH);
    attn_part<<<gattn, 128, attn_smem>>>(0);

    attn_combine<<<BT_TOTAL * HDIM / 256, 256>>>(out);
}

// round 10
// speedup vs baseline: 5.4166x; 1.0046x over previous
#include <cuda_runtime.h>

#define BATCH 8
#define TSEQ 2048
#define CDIM 768
#define HDIM 64
#define BT_TOTAL (BATCH*TSEQ)
#define NSPLIT 2

// Projected Q, K (natural [b][s][h]) and V (TRANSPOSED [b][h][s]).
// All values already tf32-RNA-rounded; Q pre-scaled by 0.125*log2(e).
__device__ float g_q[BT_TOTAL*HDIM];
__device__ float g_k[BT_TOTAL*HDIM];
__device__ float g_v[BT_TOTAL*HDIM];
// split-K partials
__device__ float g_po[NSPLIT*BT_TOTAL*HDIM];
__device__ float g_pm[NSPLIT*BT_TOTAL];
__device__ float g_pl[NSPLIT*BT_TOTAL];
// W, pre-rounded (Wq pre-scaled), stored as per-chunk swizzled smem images:
// g_wt[chunk][n*32 + ((kg*4) ^ ((n&7)<<2)) + rem]
__device__ float g_wt[3*HDIM*CDIM];

// ---------------------------------------------------------------------------
__device__ __forceinline__ unsigned f2tf(float f) {
    unsigned u;
    asm("cvt.rna.tf32.f32 %0, %1;" : "=r"(u) : "f"(f));
    return u;
}
__device__ __forceinline__ float f2tff(float f) { return __uint_as_float(f2tf(f)); }

__device__ __forceinline__ void mma_tf32(float c[4],
                                         unsigned a0, unsigned a1, unsigned a2, unsigned a3,
                                         unsigned b0, unsigned b1) {
    asm volatile(
        "mma.sync.aligned.m16n8k8.row.col.f32.tf32.tf32.f32 "
        "{%0,%1,%2,%3},{%4,%5,%6,%7},{%8,%9},{%0,%1,%2,%3};"
        : "+f"(c[0]), "+f"(c[1]), "+f"(c[2]), "+f"(c[3])
        : "r"(a0), "r"(a1), "r"(a2), "r"(a3), "r"(b0), "r"(b1));
}

__device__ __forceinline__ void ldsm4(unsigned &r0, unsigned &r1, unsigned &r2, unsigned &r3,
                                      const float* p) {
    unsigned a = (unsigned)__cvta_generic_to_shared(p);
    asm volatile("ldmatrix.sync.aligned.m8n8.x4.shared.b16 {%0,%1,%2,%3}, [%4];"
                 : "=r"(r0), "=r"(r1), "=r"(r2), "=r"(r3) : "r"(a));
}

__device__ __forceinline__ void cpasync16(float* dst, const float* src) {
    unsigned a = (unsigned)__cvta_generic_to_shared(dst);
    asm volatile("cp.async.cg.shared.global [%0], [%1], 16;" :: "r"(a), "l"(src));
}
#define CP_COMMIT() asm volatile("cp.async.commit_group;")
template<int N> __device__ __forceinline__ void cp_wait() {
    asm volatile("cp.async.wait_group %0;" :: "n"(N));
}

// ---------------------------------------------------------------------------
// Kernel 0: W prep. Round to tf32 (Wq pre-scaled by 0.125*log2e), write in
// the per-chunk swizzled layout proj stages from.
// ---------------------------------------------------------------------------
__global__ __launch_bounds__(256) void w_prep(const float* __restrict__ Wq,
                                              const float* __restrict__ Wk,
                                              const float* __restrict__ Wv)
{
    int idx = blockIdx.x * 256 + threadIdx.x;        // over 768*192
    int k = idx / 192;
    int n = idx - k * 192;
    const float* W = (n < 64) ? Wq : (n < 128) ? Wk : Wv;
    float v = W[(size_t)k * HDIM + (n & 63)];
    if (n < 64) v *= 0.18033688011112042f;           // 0.125 * log2(e)
    int chunk = k >> 5;
    int kin = k & 31;
    int kg = kin >> 2, rem = kin & 3;
    g_wt[chunk * 6144 + n * 32 + ((kg * 4) ^ ((n & 7) << 2)) + rem] = f2tff(v);
}

// ---------------------------------------------------------------------------
// Kernel 1: FUSED QKV projection. CTA tile M=64 x N=192, 8 warps (2 wq x 4 wn),
// warp tile m32 x n48. K-chunk 32. W staged via cp.async from pre-swizzled
// g_wt (3-stage ring, distance-2 prefetch ISSUED AFTER THE BARRIER); x staged
// LDG+cvt+STS (2-stage).
// ---------------------------------------------------------------------------
#define XP 36
#define XS_F (64 * XP)        // 2304 floats per x stage
#define WS_F (192 * 32)       // 6144 floats per W stage

__global__ __launch_bounds__(256, 2) void qkv_proj(const float* __restrict__ x)
{
    extern __shared__ float psm[];
    float* Xst[2] = { psm, psm + XS_F };
    float* Wst[3] = { psm + 2*XS_F, psm + 2*XS_F + WS_F, psm + 2*XS_F + 2*WS_F };

    const int tid  = threadIdx.x;
    const int w    = tid >> 5;
    const int lane = tid & 31;
    const int wq   = w & 1;
    const int wn   = w >> 1;
    const int mw   = wq * 32;
    const int lrow = lane & 7;

    const int idxA = ((((lane >> 3) & 1) * 8 + lrow)) * XP + ((lane >> 4) & 1) * 4;
    const int nr   = ((lane >> 4) & 1) * 8 + lrow;
    const int kb   = ((lane >> 3) & 1) * 4;
    const int xrs  = lrow << 2;

    const size_t m0 = (size_t)blockIdx.x * 64;

    // x staging: 2048 floats, 2 float4/thread
    const int xr0 = tid >> 3,         xc0 = (tid & 7) * 4;
    const int xr1 = (tid + 256) >> 3, xc1 = (tid & 7) * 4;
    // W staging: 6 cp.async x 16B per thread, contiguous image copy
    const int woff = tid * 4;

    float4 xg[2];

    auto ldg_x = [&](int kc) {
        xg[0] = *(const float4*)(x + (m0 + xr0) * CDIM + kc + xc0);
        xg[1] = *(const float4*)(x + (m0 + xr1) * CDIM + kc + xc1);
    };
    auto sts_x = [&](int s) {
        float4 v0 = xg[0], v1 = xg[1];
        v0.x = f2tff(v0.x); v0.y = f2tff(v0.y); v0.z = f2tff(v0.z); v0.w = f2tff(v0.w);
        v1.x = f2tff(v1.x); v1.y = f2tff(v1.y); v1.z = f2tff(v1.z); v1.w = f2tff(v1.w);
        *(float4*)&Xst[s][xr0 * XP + xc0] = v0;
        *(float4*)&Xst[s][xr1 * XP + xc1] = v1;
    };
    auto cp_w = [&](int ch, int s) {
        const float* src = g_wt + ch * WS_F + woff;
        float* dst = Wst[s] + woff;
        #pragma unroll
        for (int rep = 0; rep < 6; rep++)
            cpasync16(dst + rep * 1024, src + rep * 1024);
    };

    float acc[2][6][4];
    #pragma unroll
    for (int im = 0; im < 2; im++)
        #pragma unroll
        for (int j = 0; j < 6; j++)
            #pragma unroll
            for (int c = 0; c < 4; c++) acc[im][j][c] = 0.0f;

    // prologue: W0, W1 in flight; x0 staged
    cp_w(0, 0); CP_COMMIT();
    cp_w(1, 1); CP_COMMIT();
    ldg_x(0);
    sts_x(0);

    const int NCH = CDIM / 32;   // 24
    for (int ch = 0; ch < NCH; ch++) {
        const int sx = ch & 1;
        const int sw = ch % 3;
        if (ch + 1 < NCH) ldg_x((ch + 1) * 32);

        cp_wait<1>();            // own portion of W(ch) resident (W(ch+1) may fly)
        __syncthreads();         // visibility of all threads' W(ch); stage (ch-1)%3 free

        // Now safe: stage (ch+2)%3 == (ch-1)%3 was last read before the barrier.
        if (ch + 2 < NCH) cp_w(ch + 2, (ch + 2) % 3);
        CP_COMMIT();             // one group per iteration (maybe empty)

        const float* Xs = Xst[sx];
        const float* Ws = Wst[sw];

        #pragma unroll
        for (int ks = 0; ks < 4; ks++) {
            const int kk = ks * 8;
            unsigned a00, a01, a02, a03, a10, a11, a12, a13;
            ldsm4(a00, a01, a02, a03, Xs + (mw)      * XP + kk + idxA);
            ldsm4(a10, a11, a12, a13, Xs + (mw + 16) * XP + kk + idxA);
            const int koff = (kk + kb) ^ xrs;
            #pragma unroll
            for (int j0 = 0; j0 < 6; j0 += 2) {
                unsigned b00, b10, b01, b11;
                ldsm4(b00, b10, b01, b11,
                      Ws + (wn * 48 + j0 * 8 + nr) * 32 + koff);
                mma_tf32(acc[0][j0],     a00, a01, a02, a03, b00, b10);
                mma_tf32(acc[0][j0 + 1], a00, a01, a02, a03, b01, b11);
                mma_tf32(acc[1][j0],     a10, a11, a12, a13, b00, b10);
                mma_tf32(acc[1][j0 + 1], a10, a11, a12, a13, b01, b11);
            }
        }
        if (ch + 1 < NCH) sts_x(sx ^ 1);
    }

    // ---- store ----
    const int g = lane >> 2, t = lane & 3;
    const int bb = (int)(m0 >> 11);

    #pragma unroll
    for (int im = 0; im < 2; im++) {
        const size_t rb = m0 + mw + im * 16 + g;
        const int s0 = ((int)m0 & 2047) + mw + im * 16 + g;
        #pragma unroll
        for (int j = 0; j < 6; j++) {
            int n   = wn * 48 + j * 8;
            int mat = n >> 6;
            int col = (n & 63) + 2 * t;
            if (mat == 0) {
                *(float2*)(g_q + rb       * HDIM + col) =
                    make_float2(f2tff(acc[im][j][0]), f2tff(acc[im][j][1]));
                *(float2*)(g_q + (rb + 8) * HDIM + col) =
                    make_float2(f2tff(acc[im][j][2]), f2tff(acc[im][j][3]));
            } else if (mat == 1) {
                *(float2*)(g_k + rb       * HDIM + col) =
                    make_float2(f2tff(acc[im][j][0]), f2tff(acc[im][j][1]));
                *(float2*)(g_k + (rb + 8) * HDIM + col) =
                    make_float2(f2tff(acc[im][j][2]), f2tff(acc[im][j][3]));
            } else {
                g_v[((size_t)bb * 64 + col)     * TSEQ + s0]     = f2tff(acc[im][j][0]);
                g_v[((size_t)bb * 64 + col + 1) * TSEQ + s0]     = f2tff(acc[im][j][1]);
                g_v[((size_t)bb * 64 + col)     * TSEQ + s0 + 8] = f2tff(acc[im][j][2]);
                g_v[((size_t)bb * 64 + col + 1) * TSEQ + s0 + 8] = f2tff(acc[im][j][3]);
            }
        }
    }
}

// ---------------------------------------------------------------------------
// Kernel 2: split-K causal flash attention partials (unchanged from R8 PASS).
// ---------------------------------------------------------------------------
#define ATF 4096   // floats per 64x64 tile

__global__ __launch_bounds__(128, 3) void attn_part(int dummy)
{
    extern __shared__ float sm[];
    float* Vs  = sm + 2 * ATF;
    float* QPs = sm + 3 * ATF;

    const int tid  = threadIdx.x;
    const int w    = tid >> 5;
    const int lane = tid & 31;
    const int g    = lane >> 2;
    const int t    = lane & 3;
    const int b    = blockIdx.y;
    const int qt    = 31 - (blockIdx.x >> 1);
    const int split = blockIdx.x & 1;
    const int mw   = w * 16;
    const int lrow = lane & 7;

    const int nkv  = qt + 1;
    const int half = nkv >> 1;
    const int kt0  = split ? half : 0;
    const int kt1  = split ? nkv  : half;

    const size_t rbase = (size_t)split * BT_TOTAL + (size_t)b * TSEQ + qt * 64;

    if (kt0 == kt1) {
        for (int e = tid; e < 64 * HDIM; e += 128)
            g_po[(rbase + (e >> 6)) * HDIM + (e & 63)] = 0.0f;
        for (int r = tid; r < 64; r += 128) {
            g_pm[rbase + r] = -1e30f;
            g_pl[rbase + r] = 0.0f;
        }
        return;
    }

    const int arA = ((lane >> 3) & 1) * 8 + lrow;
    const int kaA = ((lane >> 4) & 1) * 4;
    const int nrB = ((lane >> 4) & 1) * 8 + lrow;
    const int kbB = ((lane >> 3) & 1) * 4;
    const int xsw = lrow << 2;

    const float* kb = g_k + (size_t)b * TSEQ * HDIM;
    const float* vb = g_v + (size_t)b * HDIM * TSEQ;

    auto ld_tile = [&](float* dst, const float* src, int pitch) {
        #pragma unroll
        for (int rep = 0; rep < 8; rep++) {
            int e = tid + rep * 128;
            int r = e >> 4, c4 = (e & 15) * 4;
            cpasync16(&dst[r * 64 + (c4 ^ ((r & 7) << 2))], src + r * pitch + c4);
        }
    };

    ld_tile(QPs, g_q + ((size_t)b * TSEQ + qt * 64) * HDIM, HDIM);
    CP_COMMIT();
    ld_tile(sm, kb + (size_t)kt0 * 64 * HDIM, HDIM);
    CP_COMMIT();
    ld_tile(Vs, vb + kt0 * 64, TSEQ);
    CP_COMMIT();
    cp_wait<2>();
    __syncthreads();

    unsigned qa[8][4];
    #pragma unroll
    for (int ks = 0; ks < 8; ks++)
        ldsm4(qa[ks][0], qa[ks][1], qa[ks][2], qa[ks][3],
              QPs + (mw + arA) * 64 + ((ks * 8 + kaA) ^ xsw));

    float m_i[2] = {-1e30f, -1e30f};
    float l_i[2] = {0.0f, 0.0f};
    float o[8][4];
    #pragma unroll
    for (int j = 0; j < 8; j++)
        #pragma unroll
        for (int c = 0; c < 4; c++) o[j][c] = 0.0f;

    const int niter = kt1 - kt0;
    for (int i = 0; i < niter; i++) {
        const int kt = kt0 + i;
        const int s  = i & 1;
        if (i + 1 < niter)
            ld_tile(sm + (s ^ 1) * ATF, kb + (size_t)(kt + 1) * 64 * HDIM, HDIM);
        CP_COMMIT();
        cp_wait<2>();
        __syncthreads();

        const float* Ks = sm + s * ATF;

        float sc[8][4];
        #pragma unroll
        for (int j = 0; j < 8; j++)
            #pragma unroll
            for (int c = 0; c < 4; c++) sc[j][c] = 0.0f;

        #pragma unroll
        for (int ks = 0; ks < 8; ks++) {
            const int koff = (ks * 8 + kbB) ^ xsw;
            #pragma unroll
            for (int j0 = 0; j0 < 8; j0 += 2) {
                unsigned b00, b10, b01, b11;
                ldsm4(b00, b10, b01, b11, Ks + (j0 * 8 + nrB) * 64 + koff);
                mma_tf32(sc[j0],     qa[ks][0], qa[ks][1], qa[ks][2], qa[ks][3], b00, b10);
                mma_tf32(sc[j0 + 1], qa[ks][0], qa[ks][1], qa[ks][2], qa[ks][3], b01, b11);
            }
        }

        if (kt == qt) {
            #pragma unroll
            for (int j = 0; j < 8; j++)
                #pragma unroll
                for (int c = 0; c < 4; c++) {
                    int col = j * 8 + 2 * t + (c & 1);
                    int row = mw + g + ((c >> 1) << 3);
                    if (col > row) sc[j][c] = -1e30f;
                }
        }

        #pragma unroll
        for (int h = 0; h < 2; h++) {
            const int c0 = h * 2, c1 = h * 2 + 1;
            float mx = -1e30f;
            #pragma unroll
            for (int j = 0; j < 8; j++)
                mx = fmaxf(mx, fmaxf(sc[j][c0], sc[j][c1]));
            mx = fmaxf(mx, __shfl_xor_sync(0xffffffffu, mx, 1));
            mx = fmaxf(mx, __shfl_xor_sync(0xffffffffu, mx, 2));
            float mnew = fmaxf(m_i[h], mx);
            float alpha = exp2f(m_i[h] - mnew);
            float rs = 0.0f;
            #pragma unroll
            for (int j = 0; j < 8; j++) {
                sc[j][c0] = exp2f(sc[j][c0] - mnew);
                sc[j][c1] = exp2f(sc[j][c1] - mnew);
                rs += sc[j][c0] + sc[j][c1];
            }
            rs += __shfl_xor_sync(0xffffffffu, rs, 1);
            rs += __shfl_xor_sync(0xffffffffu, rs, 2);
            l_i[h] = l_i[h] * alpha + rs;
            m_i[h] = mnew;
            #pragma unroll
            for (int j = 0; j < 8; j++) { o[j][c0] *= alpha; o[j][c1] *= alpha; }
        }

        #pragma unroll
        for (int j = 0; j < 8; j++) {
            const int c   = j * 8 + 2 * t;
            const int cb  = c & ~3;
            const int rem = c & 3;
            *(float2*)&QPs[(mw + g)     * 64 + (cb ^ (g << 2)) + rem] =
                make_float2(f2tff(sc[j][0]), f2tff(sc[j][1]));
            *(float2*)&QPs[(mw + g + 8) * 64 + (cb ^ (g << 2)) + rem] =
                make_float2(f2tff(sc[j][2]), f2tff(sc[j][3]));
        }
        __syncwarp();

        cp_wait<1>();
        __syncthreads();

        #pragma unroll
        for (int ks = 0; ks < 8; ks++) {
            const int kk = ks * 8;
            unsigned a0, a1, a2, a3;
            ldsm4(a0, a1, a2, a3, QPs + (mw + arA) * 64 + ((kk + kaA) ^ xsw));
            const int koff = (kk + kbB) ^ xsw;
            #pragma unroll
            for (int j0 = 0; j0 < 8; j0 += 2) {
                unsigned b00, b10, b01, b11;
                ldsm4(b00, b10, b01, b11, Vs + (j0 * 8 + nrB) * 64 + koff);
                mma_tf32(o[j0],     a0, a1, a2, a3, b00, b10);
                mma_tf32(o[j0 + 1], a0, a1, a2, a3, b01, b11);
            }
        }
        __syncthreads();

        if (i + 1 < niter)
            ld_tile(Vs, vb + (kt + 1) * 64, TSEQ);
        CP_COMMIT();
    }

    float* po = g_po + rbase * HDIM;
    #pragma unroll
    for (int j = 0; j < 8; j++) {
        *(float2*)(po + (mw + g)     * HDIM + j * 8 + 2 * t) = make_float2(o[j][0], o[j][1]);
        *(float2*)(po + (mw + g + 8) * HDIM + j * 8 + 2 * t) = make_float2(o[j][2], o[j][3]);
    }
    if (t == 0) {
        g_pm[rbase + mw + g]     = m_i[0];
        g_pl[rbase + mw + g]     = l_i[0];
        g_pm[rbase + mw + g + 8] = m_i[1];
        g_pl[rbase + mw + g + 8] = l_i[1];
    }
}

// ---------------------------------------------------------------------------
// Kernel 3: combine splits.
// ---------------------------------------------------------------------------
__global__ __launch_bounds__(256) void attn_combine(float* __restrict__ out)
{
    int idx = blockIdx.x * 256 + threadIdx.x;
    int r = idx >> 6;
    float m0 = g_pm[r], m1 = g_pm[BT_TOTAL + r];
    float M  = fmaxf(m0, m1);
    float w0 = exp2f(m0 - M), w1 = exp2f(m1 - M);
    float l  = g_pl[r] * w0 + g_pl[BT_TOTAL + r] * w1;
    float v  = g_po[idx] * w0 + g_po[(size_t)BT_TOTAL * HDIM + idx] * w1;
    out[idx] = v / l;
}

// ---------------------------------------------------------------------------
extern "C" void kernel_launch(void* const* d_in, const int* in_sizes, int n_in,
                              void* d_out, int out_size)
{
    (void)in_sizes; (void)n_in; (void)out_size;
    const float* x  = (const float*)d_in[0];
    const float* Wq = (const float*)d_in[1];
    const float* Wk = (const float*)d_in[2];
    const float* Wv = (const float*)d_in[3];
    float* out = (float*)d_out;

    const int proj_smem = (2 * XS_F + 3 * WS_F) * (int)sizeof(float);  // 92160
    cudaFuncSetAttribute(qkv_proj, cudaFuncAttributeMaxDynamicSharedMemorySize,
                         proj_smem);
    const int attn_smem = 4 * ATF * (int)sizeof(float);                // 65536
    cudaFuncSetAttribute(attn_part, cudaFuncAttributeMaxDynamicSharedMemorySize,
                         attn_smem);

    w_prep<<<(3 * HDIM * CDIM) / 256, 256>>>(Wq, Wk, Wv);

    qkv_proj<<<BT_TOTAL / 64, 256, proj_smem>>>(x);

    dim3 gattn(2 * TSEQ / 64, BATCH);
    attn_part<<<gattn, 128, attn_smem>>>(0);

    attn_combine<<<BT_TOTAL * HDIM / 256, 256>>>(out);
}